// round 12
// baseline (speedup 1.0000x reference)
#include <cuda_runtime.h>
#include <cstdint>
#include <cstddef>

#define T_SEQ 2048
#define NH 16
#define HD 64
#define C_DIM 1024
#define QKV_N 3072
#define QK_N 2048
#define CHUNK 128
#define NCHUNK (T_SEQ / CHUNK)

// ---------------- scratch (static __device__, no allocs) ----------------
__device__ float  g_qk[T_SEQ * QK_N];            // raw q|k per head (128/head)
__device__ float  g_vt[T_SEQ * C_DIM];           // raw v (head-minor cols)
__device__ float  g_Q[NH * T_SEQ * HD];
__device__ float  g_K[NH * T_SEQ * HD];
__device__ float  g_V[NH * T_SEQ * HD];
__device__ float  g_KVc[NH * NCHUNK * HD * HD];
__device__ double g_Ksc[NH * NCHUNK * HD];
__device__ float  g_Vsc[NH * NCHUNK * HD];
__device__ float  g_Y[T_SEQ * C_DIM];

// ====== SIMT fp32 NT GEMM, gathered-B for q/k (bit-identical math) ======
// C[M, 2048] = A[M,K] * Bg^T where Bg row n = w_attn row (n>>7)*192+(n&127)
__global__ __launch_bounds__(256) void sgemm_qk(
    const float* __restrict__ A, const float* __restrict__ B,
    float* __restrict__ C, int M, int N, int K) {
    __shared__ float As[8][128];
    __shared__ float Bs[8][128];
    const int bm = blockIdx.y * 128;
    const int bn = blockIdx.x * 128;
    const int tid = threadIdx.x;
    const int tx = tid & 15;
    const int ty = tid >> 4;
    const int lr = tid >> 1;
    const int lk = (tid & 1) << 2;

    const int gb = bn + lr;
    const int brow = ((gb >> 7) * 192) + (gb & 127);
    const float* Ap = A + (size_t)(bm + lr) * K + lk;
    const float* Bp = B + (size_t)brow * K + lk;

    float acc[8][8];
#pragma unroll
    for (int i = 0; i < 8; i++)
#pragma unroll
        for (int j = 0; j < 8; j++) acc[i][j] = 0.0f;

    for (int k0 = 0; k0 < K; k0 += 8) {
        float4 a4 = *(const float4*)(Ap + k0);
        float4 b4 = *(const float4*)(Bp + k0);
        As[lk + 0][lr] = a4.x; As[lk + 1][lr] = a4.y;
        As[lk + 2][lr] = a4.z; As[lk + 3][lr] = a4.w;
        Bs[lk + 0][lr] = b4.x; Bs[lk + 1][lr] = b4.y;
        Bs[lk + 2][lr] = b4.z; Bs[lk + 3][lr] = b4.w;
        __syncthreads();
#pragma unroll
        for (int kk = 0; kk < 8; kk++) {
            float a[8], b[8];
            *(float4*)&a[0] = *(const float4*)&As[kk][ty * 8];
            *(float4*)&a[4] = *(const float4*)&As[kk][ty * 8 + 4];
            *(float4*)&b[0] = *(const float4*)&Bs[kk][tx * 8];
            *(float4*)&b[4] = *(const float4*)&Bs[kk][tx * 8 + 4];
#pragma unroll
            for (int i = 0; i < 8; i++)
#pragma unroll
                for (int j = 0; j < 8; j++) acc[i][j] += a[i] * b[j];
        }
        __syncthreads();
    }
#pragma unroll
    for (int i = 0; i < 8; i++) {
        float4* cp = (float4*)(C + (size_t)(bm + ty * 8 + i) * N + bn + tx * 8);
        cp[0] = make_float4(acc[i][0], acc[i][1], acc[i][2], acc[i][3]);
        cp[1] = make_float4(acc[i][4], acc[i][5], acc[i][6], acc[i][7]);
    }
}

// =================== tf32 mma.sync helpers (sm_80+ PTX) =================
__device__ __forceinline__ void split2(float x, uint32_t& h, uint32_t& l) {
    asm("cvt.rna.tf32.f32 %0, %1;" : "=r"(h) : "f"(x));
    float r = x - __uint_as_float(h);
    asm("cvt.rna.tf32.f32 %0, %1;" : "=r"(l) : "f"(r));
}

__device__ __forceinline__ void mma_tf32(float* d, const uint32_t* a,
                                         const uint32_t* b) {
    asm volatile(
        "mma.sync.aligned.m16n8k8.row.col.f32.tf32.tf32.f32 "
        "{%0,%1,%2,%3}, {%4,%5,%6,%7}, {%8,%9}, {%0,%1,%2,%3};"
        : "+f"(d[0]), "+f"(d[1]), "+f"(d[2]), "+f"(d[3])
        : "r"(a[0]), "r"(a[1]), "r"(a[2]), "r"(a[3]), "r"(b[0]), "r"(b[1]));
}

#define CP_ASYNC16(dst, src) \
    asm volatile("cp.async.cg.shared.global [%0], [%1], 16;" \
                 :: "r"(dst), "l"(src))
#define CP_COMMIT() asm volatile("cp.async.commit_group;" ::: "memory")
#define CP_WAIT1()  asm volatile("cp.async.wait_group 1;" ::: "memory")
#define CP_WAIT0()  asm volatile("cp.async.wait_group 0;" ::: "memory")

// ======= tf32 mma NT GEMM (3-product).  REMAP=1: B row gathered for v ===
template <int REMAP>
__global__ __launch_bounds__(256, 1) void gemm_mma3(
    const float* __restrict__ A, const float* __restrict__ B,
    float* __restrict__ C, int M, int N, int K) {
    extern __shared__ float smf[];
    float* As = smf;
    float* Bs = smf + 8192;
    const uint32_t smA_u32 = (uint32_t)__cvta_generic_to_shared(As);
    const uint32_t smB_u32 = (uint32_t)__cvta_generic_to_shared(Bs);

    const int tid = threadIdx.x;
    const int wid = tid >> 5;
    const int lane = tid & 31;
    const int bm = blockIdx.y * 128;
    const int bn = blockIdx.x * 128;
    const int warpM = (wid >> 2) * 64;
    const int warpN = (wid & 3) * 32;
    const int nk = K >> 5;

    const int lr = tid >> 1;
    const int j0 = (tid & 1) * 4;
    const int lrx = lr & 7;
    const int gb = bn + lr;
    const int brow = REMAP ? (((gb >> 6) * 192) + 128 + (gb & 63)) : gb;
    const float* Asrc = A + (size_t)(bm + lr) * K;
    const float* Bsrc = B + (size_t)brow * K;

    float acc[4][4][4];
#pragma unroll
    for (int mt = 0; mt < 4; mt++)
#pragma unroll
        for (int nt = 0; nt < 4; nt++)
#pragma unroll
            for (int u = 0; u < 4; u++) acc[mt][nt][u] = 0.0f;

    {
        const uint32_t ab = smA_u32 + lr * 128;
        const uint32_t bb = smB_u32 + lr * 128;
#pragma unroll
        for (int j = 0; j < 4; j++) {
            int c4 = j0 + j;
            int swc = (c4 ^ lrx) * 16;
            CP_ASYNC16(ab + swc, Asrc + c4 * 4);
            CP_ASYNC16(bb + swc, Bsrc + c4 * 4);
        }
        CP_COMMIT();
    }

    for (int it = 0; it < nk; it++) {
        if (it + 1 < nk) {
            const int nb = (it + 1) & 1;
            const int kblk = (it + 1) << 5;
            const uint32_t ab = smA_u32 + nb * 16384 + lr * 128;
            const uint32_t bb = smB_u32 + nb * 16384 + lr * 128;
#pragma unroll
            for (int j = 0; j < 4; j++) {
                int c4 = j0 + j;
                int swc = (c4 ^ lrx) * 16;
                CP_ASYNC16(ab + swc, Asrc + kblk + c4 * 4);
                CP_ASYNC16(bb + swc, Bsrc + kblk + c4 * 4);
            }
            CP_COMMIT();
            CP_WAIT1();
        } else {
            CP_WAIT0();
        }
        __syncthreads();

        const float* Ab = As + (it & 1) * 4096;
        const float* Bb = Bs + (it & 1) * 4096;
#pragma unroll
        for (int ks = 0; ks < 4; ks++) {
            uint32_t bh[4][2], bl[4][2];
#pragma unroll
            for (int nt = 0; nt < 4; nt++) {
                int n0 = warpN + nt * 8 + (lane >> 2);
                const float* bp = Bb + n0 * 32;
                int s0 = ((2 * ks) ^ (n0 & 7)) * 4 + (lane & 3);
                int s1 = ((2 * ks + 1) ^ (n0 & 7)) * 4 + (lane & 3);
                split2(bp[s0], bh[nt][0], bl[nt][0]);
                split2(bp[s1], bh[nt][1], bl[nt][1]);
            }
#pragma unroll
            for (int mt = 0; mt < 4; mt++) {
                int r0 = warpM + mt * 16 + (lane >> 2);
                const float* ap0 = Ab + r0 * 32;
                const float* ap1 = ap0 + 8 * 32;
                int s0 = ((2 * ks) ^ (r0 & 7)) * 4 + (lane & 3);
                int s1 = ((2 * ks + 1) ^ (r0 & 7)) * 4 + (lane & 3);
                uint32_t ah[4], al[4];
                split2(ap0[s0], ah[0], al[0]);
                split2(ap1[s0], ah[1], al[1]);
                split2(ap0[s1], ah[2], al[2]);
                split2(ap1[s1], ah[3], al[3]);
#pragma unroll
                for (int nt = 0; nt < 4; nt++) {
                    mma_tf32(acc[mt][nt], ah, bh[nt]);
                    mma_tf32(acc[mt][nt], ah, bl[nt]);
                    mma_tf32(acc[mt][nt], al, bh[nt]);
                }
            }
        }
        __syncthreads();
    }

#pragma unroll
    for (int mt = 0; mt < 4; mt++) {
        int r0 = bm + warpM + mt * 16 + (lane >> 2);
#pragma unroll
        for (int nt = 0; nt < 4; nt++) {
            int cc = bn + warpN + nt * 8 + 2 * (lane & 3);
            *(float2*)(C + (size_t)r0 * N + cc) =
                make_float2(acc[mt][nt][0], acc[mt][nt][1]);
            *(float2*)(C + (size_t)(r0 + 8) * N + cc) =
                make_float2(acc[mt][nt][2], acc[mt][nt][3]);
        }
    }
}

// ---------------- RoPE + scatter to head-major Q/K/V --------------------
__global__ __launch_bounds__(256) void rope_scatter2(
    const float* __restrict__ cosb, const float* __restrict__ sinb) {
    int tid = blockIdx.x * blockDim.x + threadIdx.x;
    if (tid >= T_SEQ * NH * HD) return;
    int d = tid & 63;
    int h = (tid >> 6) & 15;
    int t = tid >> 10;
    const float* row = g_qk + (size_t)t * QK_N + h * 128;
    float c = cosb[t * HD + d];
    float s = sinb[t * HD + d];
    int pd = (d < 32) ? d + 32 : d - 32;
    float sgn = (d < 32) ? -1.0f : 1.0f;

    float q = row[d];
    float qr = sgn * row[pd];
    float k = row[64 + d];
    float kr = sgn * row[64 + pd];
    size_t o = ((size_t)h * T_SEQ + t) * HD + d;
    g_Q[o] = q * c + qr * s;
    g_K[o] = k * c + kr * s;
    g_V[o] = g_vt[(size_t)t * C_DIM + h * HD + d];
}

// ---------------- per-chunk sums: KV outer, Ksum(fp64), Vsum ------------
__global__ __launch_bounds__(256) void chunk_sums() {
    extern __shared__ float smf2[];
    float* Ks = smf2;
    float* Vs = smf2 + CHUNK * HD;
    const int c = blockIdx.x, h = blockIdx.y, tid = threadIdx.x;
    const float* Kg = g_K + ((size_t)h * T_SEQ + c * CHUNK) * HD;
    const float* Vg = g_V + ((size_t)h * T_SEQ + c * CHUNK) * HD;
    for (int it = tid; it < CHUNK * HD / 4; it += 256) {
        ((float4*)Ks)[it] = ((const float4*)Kg)[it];
        ((float4*)Vs)[it] = ((const float4*)Vg)[it];
    }
    __syncthreads();

    const int d0 = tid >> 2;
    const int e0 = (tid & 3) * 16;
    float acc[16];
#pragma unroll
    for (int u = 0; u < 16; u++) acc[u] = 0.0f;
    for (int j = 0; j < CHUNK; j++) {
        float kd = Ks[j * HD + d0];
#pragma unroll
        for (int u = 0; u < 16; u++) acc[u] += kd * Vs[j * HD + e0 + u];
    }
    float* out = g_KVc + ((size_t)h * NCHUNK + c) * (HD * HD) + d0 * HD + e0;
#pragma unroll
    for (int u = 0; u < 4; u++)
        ((float4*)out)[u] = make_float4(acc[4 * u], acc[4 * u + 1],
                                        acc[4 * u + 2], acc[4 * u + 3]);
    if (tid < HD) {
        double s0 = 0.0, s1 = 0.0;
        for (int j = 0; j < CHUNK; j += 2) {
            s0 += (double)Ks[j * HD + tid];
            s1 += (double)Ks[(j + 1) * HD + tid];
        }
        g_Ksc[((size_t)h * NCHUNK + c) * HD + tid] = s0 + s1;
    } else if (tid < 2 * HD) {
        int e = tid - HD;
        float s = 0.0f;
        for (int j = 0; j < CHUNK; j++) s += Vs[j * HD + e];
        g_Vsc[((size_t)h * NCHUNK + c) * HD + e] = s;
    }
}

// ---------------- per-chunk attention (512 threads, no kcum) ------------
// den_i = c*128 + fp64(q_i . Ksp) + fp64-sum over j of fp32 score row
__global__ __launch_bounds__(512) void chunk_attn() {
    extern __shared__ char smraw[];
    double* KspD = (double*)smraw;            // [64]
    double* denD = KspD + HD;                 // [128]
    float* Qst = (float*)(denD + CHUNK);      // [64][128] d-major
    float* Kst = Qst + HD * CHUNK;            // [64][128]
    float* Vs  = Kst + HD * CHUNK;            // [128][64]
    float* Sct = Vs + CHUNK * HD;             // [128][128]  Sct[j][i]
    float* KVp = Sct + CHUNK * CHUNK;         // [64][64]
    float* Vsp = KVp + HD * HD;               // [64]

    const int c = blockIdx.x, h = blockIdx.y, tid = threadIdx.x;
    const float* Qg = g_Q + ((size_t)h * T_SEQ + c * CHUNK) * HD;
    const float* Kg = g_K + ((size_t)h * T_SEQ + c * CHUNK) * HD;
    const float* Vg = g_V + ((size_t)h * T_SEQ + c * CHUNK) * HD;

    // load Q,K transposed; V natural (stride 512)
    for (int it = tid; it < CHUNK * HD / 4; it += 512) {
        int t = it >> 4;
        int d4 = (it & 15) * 4;
        float4 q4 = ((const float4*)(Qg + t * HD))[it & 15];
        float4 k4 = ((const float4*)(Kg + t * HD))[it & 15];
        Qst[(d4 + 0) * CHUNK + t] = q4.x; Qst[(d4 + 1) * CHUNK + t] = q4.y;
        Qst[(d4 + 2) * CHUNK + t] = q4.z; Qst[(d4 + 3) * CHUNK + t] = q4.w;
        Kst[(d4 + 0) * CHUNK + t] = k4.x; Kst[(d4 + 1) * CHUNK + t] = k4.y;
        Kst[(d4 + 2) * CHUNK + t] = k4.z; Kst[(d4 + 3) * CHUNK + t] = k4.w;
        ((float4*)Vs)[it] = ((const float4*)Vg)[it];
    }

    // prefix state
    {
        float kv[8];
#pragma unroll
        for (int u = 0; u < 8; u++) kv[u] = 0.0f;
        for (int cp = 0; cp < c; cp++) {
            const float* p = g_KVc + ((size_t)h * NCHUNK + cp) * (HD * HD) + tid * 8;
#pragma unroll
            for (int u = 0; u < 8; u++) kv[u] += p[u];
        }
#pragma unroll
        for (int u = 0; u < 8; u++) KVp[tid * 8 + u] = kv[u];
        if (tid < HD) {
            double s = 0.0;
            for (int cp = 0; cp < c; cp++)
                s += g_Ksc[((size_t)h * NCHUNK + cp) * HD + tid];
            KspD[tid] = s;
        } else if (tid < 2 * HD) {
            int e = tid - HD;
            float s = 0.0f;
            for (int cp = 0; cp < c; cp++)
                s += g_Vsc[((size_t)h * NCHUNK + cp) * HD + e];
            Vsp[e] = s;
        }
    }
    __syncthreads();

    // scores: Sct[j][i] = (j<=i) ? 1 + q_i . k_j : 0   (4x8 tiles, 512 thr)
    {
        const int tx = tid & 15;       // -> i group of 8
        const int ty = tid >> 4;       // -> j group of 4 (0..31)
        const int i0 = tx * 8, j0 = ty * 4;
        float acc[4][8];
#pragma unroll
        for (int jj = 0; jj < 4; jj++)
#pragma unroll
            for (int ii = 0; ii < 8; ii++) acc[jj][ii] = 1.0f;
        for (int d = 0; d < HD; d++) {
            float q[8], k[4];
            *(float4*)&q[0] = *(const float4*)&Qst[d * CHUNK + i0];
            *(float4*)&q[4] = *(const float4*)&Qst[d * CHUNK + i0 + 4];
            *(float4*)&k[0] = *(const float4*)&Kst[d * CHUNK + j0];
#pragma unroll
            for (int jj = 0; jj < 4; jj++)
#pragma unroll
                for (int ii = 0; ii < 8; ii++) acc[jj][ii] += k[jj] * q[ii];
        }
#pragma unroll
        for (int jj = 0; jj < 4; jj++) {
            int j = j0 + jj;
            float v[8];
#pragma unroll
            for (int ii = 0; ii < 8; ii++)
                v[ii] = (j <= i0 + ii) ? acc[jj][ii] : 0.0f;
            float4* sp = (float4*)&Sct[j * CHUNK + i0];
            sp[0] = make_float4(v[0], v[1], v[2], v[3]);
            sp[1] = make_float4(v[4], v[5], v[6], v[7]);
        }
    }
    __syncthreads();

    // denominators (threads 0..127), fp64
    if (tid < CHUNK) {
        const int i = tid;
        double p0 = 0.0, p1 = 0.0, p2 = 0.0, p3 = 0.0;
        for (int d = 0; d < HD; d += 4) {
            p0 += (double)Qst[(d + 0) * CHUNK + i] * KspD[d + 0];
            p1 += (double)Qst[(d + 1) * CHUNK + i] * KspD[d + 1];
            p2 += (double)Qst[(d + 2) * CHUNK + i] * KspD[d + 2];
            p3 += (double)Qst[(d + 3) * CHUNK + i] * KspD[d + 3];
        }
        double s0 = 0.0, s1 = 0.0, s2 = 0.0, s3 = 0.0;
        for (int j = 0; j < CHUNK; j += 4) {
            s0 += (double)Sct[(j + 0) * CHUNK + i];
            s1 += (double)Sct[(j + 1) * CHUNK + i];
            s2 += (double)Sct[(j + 2) * CHUNK + i];
            s3 += (double)Sct[(j + 3) * CHUNK + i];
        }
        denD[i] = (double)(c * CHUNK) + ((p0 + p1) + (p2 + p3))
                  + ((s0 + s1) + (s2 + s3));
    }
    __syncthreads();

    // numerators: 4x4 tiles, 512 threads
    {
        const int ti = tid >> 4;        // 0..31 -> i group of 4
        const int i0 = ti * 4;
        const int e0 = (tid & 15) * 4;
        float acc[4][4];
#pragma unroll
        for (int ii = 0; ii < 4; ii++)
#pragma unroll
            for (int ee = 0; ee < 4; ee++) acc[ii][ee] = 0.0f;
        for (int d = 0; d < HD; d++) {
            float q[4], kv[4];
            *(float4*)&q[0] = *(const float4*)&Qst[d * CHUNK + i0];
            *(float4*)&kv[0] = *(const float4*)&KVp[d * HD + e0];
#pragma unroll
            for (int ii = 0; ii < 4; ii++)
#pragma unroll
                for (int ee = 0; ee < 4; ee++) acc[ii][ee] += q[ii] * kv[ee];
        }
        for (int j = 0; j < CHUNK; j++) {
            float sv[4], v[4];
            *(float4*)&sv[0] = *(const float4*)&Sct[j * CHUNK + i0];
            *(float4*)&v[0] = *(const float4*)&Vs[j * HD + e0];
#pragma unroll
            for (int ii = 0; ii < 4; ii++)
#pragma unroll
                for (int ee = 0; ee < 4; ee++) acc[ii][ee] += sv[ii] * v[ee];
        }
#pragma unroll
        for (int ii = 0; ii < 4; ii++) {
            int i = i0 + ii;
            int t = c * CHUNK + i;
            double inv = 1.0 / denD[i];
            float o[4];
#pragma unroll
            for (int ee = 0; ee < 4; ee++)
                o[ee] = (float)((double)(acc[ii][ee] + Vsp[e0 + ee]) * inv);
            *(float4*)(g_Y + (size_t)t * C_DIM + h * HD + e0) =
                make_float4(o[0], o[1], o[2], o[3]);
        }
    }
}

// ---------------- launch ------------------------------------------------
extern "C" void kernel_launch(void* const* d_in, const int* in_sizes, int n_in,
                              void* d_out, int out_size) {
    const float* x      = (const float*)d_in[0];
    const float* w_attn = (const float*)d_in[1];
    const float* w_proj = (const float*)d_in[2];
    const float* cosb   = (const float*)d_in[3];
    const float* sinb   = (const float*)d_in[4];
    float* out = (float*)d_out;

    void *p_qk, *p_vt, *p_Y;
    cudaGetSymbolAddress(&p_qk, g_qk);
    cudaGetSymbolAddress(&p_vt, g_vt);
    cudaGetSymbolAddress(&p_Y, g_Y);

    int smem_gemm = 16384 * 4;
    int smem_sums = 2 * CHUNK * HD * (int)sizeof(float);
    int smem_attn = (int)(sizeof(double) * (HD + CHUNK)) +
                    (int)(sizeof(float) *
                          (3 * CHUNK * HD + CHUNK * CHUNK + HD * HD + HD));
    cudaFuncSetAttribute(gemm_mma3<0>, cudaFuncAttributeMaxDynamicSharedMemorySize,
                         smem_gemm);
    cudaFuncSetAttribute(gemm_mma3<1>, cudaFuncAttributeMaxDynamicSharedMemorySize,
                         smem_gemm);
    cudaFuncSetAttribute(chunk_sums, cudaFuncAttributeMaxDynamicSharedMemorySize,
                         smem_sums);
    cudaFuncSetAttribute(chunk_attn, cudaFuncAttributeMaxDynamicSharedMemorySize,
                         smem_attn);

    // 1a) q|k = x @ w_attn_qk^T  (SIMT fp32, bit-identical q/k path)
    sgemm_qk<<<dim3(QK_N / 128, T_SEQ / 128), 256>>>(
        x, w_attn, (float*)p_qk, T_SEQ, QK_N, C_DIM);
    // 1b) v = x @ w_attn_v^T     (tf32 mma, unamplified path)
    gemm_mma3<1><<<dim3(C_DIM / 128, T_SEQ / 128), 256, smem_gemm>>>(
        x, w_attn, (float*)p_vt, T_SEQ, C_DIM, C_DIM);
    // 2) rope + scatter
    rope_scatter2<<<(T_SEQ * NH * HD + 255) / 256, 256>>>(cosb, sinb);
    // 3) chunk sums
    chunk_sums<<<dim3(NCHUNK, NH), 256, smem_sums>>>();
    // 4) chunk attention (512 threads)
    chunk_attn<<<dim3(NCHUNK, NH), 512, smem_attn>>>();
    // 5) out = Y @ w_proj^T      (tf32 mma)
    gemm_mma3<0><<<dim3(C_DIM / 128, T_SEQ / 128), 256, smem_gemm>>>(
        (const float*)p_Y, w_proj, out, T_SEQ, C_DIM, C_DIM);
}

// round 13
// speedup vs baseline: 1.4785x; 1.4785x over previous
#include <cuda_runtime.h>
#include <cstdint>
#include <cstddef>

#define T_SEQ 2048
#define NH 16
#define HD 64
#define C_DIM 1024
#define QK_N 2048
#define CHUNK 128
#define NCHUNK (T_SEQ / CHUNK)

// ---------------- scratch (static __device__, no allocs) ----------------
__device__ float  g_qk[T_SEQ * QK_N];            // raw q|k per head (128/head)
__device__ float  g_vt[T_SEQ * C_DIM];           // raw v (head-minor cols)
__device__ float  g_Q[NH * T_SEQ * HD];
__device__ float  g_K[NH * T_SEQ * HD];
__device__ float  g_V[NH * T_SEQ * HD];
__device__ float  g_KVc[NH * NCHUNK * HD * HD];
__device__ double g_Ksc[NH * NCHUNK * HD];
__device__ float  g_Vsc[NH * NCHUNK * HD];
__device__ float  g_Y[T_SEQ * C_DIM];

// ====== SIMT fp32 NT GEMM, gathered-B for q/k (bit-identical math) ======
// C[M, 2048] = A[M,K] * Bg^T where Bg row n = w_attn row (n>>7)*192+(n&127)
__global__ __launch_bounds__(256) void sgemm_qk(
    const float* __restrict__ A, const float* __restrict__ B,
    float* __restrict__ C, int M, int N, int K) {
    __shared__ float As[8][128];
    __shared__ float Bs[8][128];
    const int bm = blockIdx.y * 128;
    const int bn = blockIdx.x * 128;
    const int tid = threadIdx.x;
    const int tx = tid & 15;
    const int ty = tid >> 4;
    const int lr = tid >> 1;
    const int lk = (tid & 1) << 2;

    const int gb = bn + lr;
    const int brow = ((gb >> 7) * 192) + (gb & 127);
    const float* Ap = A + (size_t)(bm + lr) * K + lk;
    const float* Bp = B + (size_t)brow * K + lk;

    float acc[8][8];
#pragma unroll
    for (int i = 0; i < 8; i++)
#pragma unroll
        for (int j = 0; j < 8; j++) acc[i][j] = 0.0f;

    for (int k0 = 0; k0 < K; k0 += 8) {
        float4 a4 = *(const float4*)(Ap + k0);
        float4 b4 = *(const float4*)(Bp + k0);
        As[lk + 0][lr] = a4.x; As[lk + 1][lr] = a4.y;
        As[lk + 2][lr] = a4.z; As[lk + 3][lr] = a4.w;
        Bs[lk + 0][lr] = b4.x; Bs[lk + 1][lr] = b4.y;
        Bs[lk + 2][lr] = b4.z; Bs[lk + 3][lr] = b4.w;
        __syncthreads();
#pragma unroll
        for (int kk = 0; kk < 8; kk++) {
            float a[8], b[8];
            *(float4*)&a[0] = *(const float4*)&As[kk][ty * 8];
            *(float4*)&a[4] = *(const float4*)&As[kk][ty * 8 + 4];
            *(float4*)&b[0] = *(const float4*)&Bs[kk][tx * 8];
            *(float4*)&b[4] = *(const float4*)&Bs[kk][tx * 8 + 4];
#pragma unroll
            for (int i = 0; i < 8; i++)
#pragma unroll
                for (int j = 0; j < 8; j++) acc[i][j] += a[i] * b[j];
        }
        __syncthreads();
    }
#pragma unroll
    for (int i = 0; i < 8; i++) {
        float4* cp = (float4*)(C + (size_t)(bm + ty * 8 + i) * N + bn + tx * 8);
        cp[0] = make_float4(acc[i][0], acc[i][1], acc[i][2], acc[i][3]);
        cp[1] = make_float4(acc[i][4], acc[i][5], acc[i][6], acc[i][7]);
    }
}

// =================== tf32 mma.sync helpers (sm_80+ PTX) =================
__device__ __forceinline__ void split2(float x, uint32_t& h, uint32_t& l) {
    asm("cvt.rna.tf32.f32 %0, %1;" : "=r"(h) : "f"(x));
    float r = x - __uint_as_float(h);
    asm("cvt.rna.tf32.f32 %0, %1;" : "=r"(l) : "f"(r));
}

__device__ __forceinline__ void mma_tf32(float* d, const uint32_t* a,
                                         const uint32_t* b) {
    asm volatile(
        "mma.sync.aligned.m16n8k8.row.col.f32.tf32.tf32.f32 "
        "{%0,%1,%2,%3}, {%4,%5,%6,%7}, {%8,%9}, {%0,%1,%2,%3};"
        : "+f"(d[0]), "+f"(d[1]), "+f"(d[2]), "+f"(d[3])
        : "r"(a[0]), "r"(a[1]), "r"(a[2]), "r"(a[3]), "r"(b[0]), "r"(b[1]));
}

#define CP_ASYNC16(dst, src) \
    asm volatile("cp.async.cg.shared.global [%0], [%1], 16;" \
                 :: "r"(dst), "l"(src))
#define CP_COMMIT() asm volatile("cp.async.commit_group;" ::: "memory")
#define CP_WAIT1()  asm volatile("cp.async.wait_group 1;" ::: "memory")
#define CP_WAIT0()  asm volatile("cp.async.wait_group 0;" ::: "memory")

// ======= tf32 mma NT GEMM (3-product).  REMAP=1: B row gathered for v ===
template <int REMAP>
__global__ __launch_bounds__(256, 1) void gemm_mma3(
    const float* __restrict__ A, const float* __restrict__ B,
    float* __restrict__ C, int M, int N, int K) {
    extern __shared__ float smf[];
    float* As = smf;
    float* Bs = smf + 8192;
    const uint32_t smA_u32 = (uint32_t)__cvta_generic_to_shared(As);
    const uint32_t smB_u32 = (uint32_t)__cvta_generic_to_shared(Bs);

    const int tid = threadIdx.x;
    const int wid = tid >> 5;
    const int lane = tid & 31;
    const int bm = blockIdx.y * 128;
    const int bn = blockIdx.x * 128;
    const int warpM = (wid >> 2) * 64;
    const int warpN = (wid & 3) * 32;
    const int nk = K >> 5;

    const int lr = tid >> 1;
    const int j0 = (tid & 1) * 4;
    const int lrx = lr & 7;
    const int gb = bn + lr;
    const int brow = REMAP ? (((gb >> 6) * 192) + 128 + (gb & 63)) : gb;
    const float* Asrc = A + (size_t)(bm + lr) * K;
    const float* Bsrc = B + (size_t)brow * K;

    float acc[4][4][4];
#pragma unroll
    for (int mt = 0; mt < 4; mt++)
#pragma unroll
        for (int nt = 0; nt < 4; nt++)
#pragma unroll
            for (int u = 0; u < 4; u++) acc[mt][nt][u] = 0.0f;

    {
        const uint32_t ab = smA_u32 + lr * 128;
        const uint32_t bb = smB_u32 + lr * 128;
#pragma unroll
        for (int j = 0; j < 4; j++) {
            int c4 = j0 + j;
            int swc = (c4 ^ lrx) * 16;
            CP_ASYNC16(ab + swc, Asrc + c4 * 4);
            CP_ASYNC16(bb + swc, Bsrc + c4 * 4);
        }
        CP_COMMIT();
    }

    for (int it = 0; it < nk; it++) {
        if (it + 1 < nk) {
            const int nb = (it + 1) & 1;
            const int kblk = (it + 1) << 5;
            const uint32_t ab = smA_u32 + nb * 16384 + lr * 128;
            const uint32_t bb = smB_u32 + nb * 16384 + lr * 128;
#pragma unroll
            for (int j = 0; j < 4; j++) {
                int c4 = j0 + j;
                int swc = (c4 ^ lrx) * 16;
                CP_ASYNC16(ab + swc, Asrc + kblk + c4 * 4);
                CP_ASYNC16(bb + swc, Bsrc + kblk + c4 * 4);
            }
            CP_COMMIT();
            CP_WAIT1();
        } else {
            CP_WAIT0();
        }
        __syncthreads();

        const float* Ab = As + (it & 1) * 4096;
        const float* Bb = Bs + (it & 1) * 4096;
#pragma unroll
        for (int ks = 0; ks < 4; ks++) {
            uint32_t bh[4][2], bl[4][2];
#pragma unroll
            for (int nt = 0; nt < 4; nt++) {
                int n0 = warpN + nt * 8 + (lane >> 2);
                const float* bp = Bb + n0 * 32;
                int s0 = ((2 * ks) ^ (n0 & 7)) * 4 + (lane & 3);
                int s1 = ((2 * ks + 1) ^ (n0 & 7)) * 4 + (lane & 3);
                split2(bp[s0], bh[nt][0], bl[nt][0]);
                split2(bp[s1], bh[nt][1], bl[nt][1]);
            }
#pragma unroll
            for (int mt = 0; mt < 4; mt++) {
                int r0 = warpM + mt * 16 + (lane >> 2);
                const float* ap0 = Ab + r0 * 32;
                const float* ap1 = ap0 + 8 * 32;
                int s0 = ((2 * ks) ^ (r0 & 7)) * 4 + (lane & 3);
                int s1 = ((2 * ks + 1) ^ (r0 & 7)) * 4 + (lane & 3);
                uint32_t ah[4], al[4];
                split2(ap0[s0], ah[0], al[0]);
                split2(ap1[s0], ah[1], al[1]);
                split2(ap0[s1], ah[2], al[2]);
                split2(ap1[s1], ah[3], al[3]);
#pragma unroll
                for (int nt = 0; nt < 4; nt++) {
                    mma_tf32(acc[mt][nt], ah, bh[nt]);
                    mma_tf32(acc[mt][nt], ah, bl[nt]);
                    mma_tf32(acc[mt][nt], al, bh[nt]);
                }
            }
        }
        __syncthreads();
    }

#pragma unroll
    for (int mt = 0; mt < 4; mt++) {
        int r0 = bm + warpM + mt * 16 + (lane >> 2);
#pragma unroll
        for (int nt = 0; nt < 4; nt++) {
            int cc = bn + warpN + nt * 8 + 2 * (lane & 3);
            *(float2*)(C + (size_t)r0 * N + cc) =
                make_float2(acc[mt][nt][0], acc[mt][nt][1]);
            *(float2*)(C + (size_t)(r0 + 8) * N + cc) =
                make_float2(acc[mt][nt][2], acc[mt][nt][3]);
        }
    }
}

// ---------------- RoPE + scatter to head-major Q/K/V --------------------
__global__ __launch_bounds__(256) void rope_scatter2(
    const float* __restrict__ cosb, const float* __restrict__ sinb) {
    int tid = blockIdx.x * blockDim.x + threadIdx.x;
    if (tid >= T_SEQ * NH * HD) return;
    int d = tid & 63;
    int h = (tid >> 6) & 15;
    int t = tid >> 10;
    const float* row = g_qk + (size_t)t * QK_N + h * 128;
    float c = cosb[t * HD + d];
    float s = sinb[t * HD + d];
    int pd = (d < 32) ? d + 32 : d - 32;
    float sgn = (d < 32) ? -1.0f : 1.0f;

    float q = row[d];
    float qr = sgn * row[pd];
    float k = row[64 + d];
    float kr = sgn * row[64 + pd];
    size_t o = ((size_t)h * T_SEQ + t) * HD + d;
    g_Q[o] = q * c + qr * s;
    g_K[o] = k * c + kr * s;
    g_V[o] = g_vt[(size_t)t * C_DIM + h * HD + d];
}

// ---------------- per-chunk sums: KV outer, Ksum(fp64), Vsum ------------
__global__ __launch_bounds__(256) void chunk_sums() {
    extern __shared__ float smf2[];
    float* Ks = smf2;
    float* Vs = smf2 + CHUNK * HD;
    const int c = blockIdx.x, h = blockIdx.y, tid = threadIdx.x;
    const float* Kg = g_K + ((size_t)h * T_SEQ + c * CHUNK) * HD;
    const float* Vg = g_V + ((size_t)h * T_SEQ + c * CHUNK) * HD;
    for (int it = tid; it < CHUNK * HD / 4; it += 256) {
        ((float4*)Ks)[it] = ((const float4*)Kg)[it];
        ((float4*)Vs)[it] = ((const float4*)Vg)[it];
    }
    __syncthreads();

    const int d0 = tid >> 2;
    const int e0 = (tid & 3) * 16;
    float acc[16];
#pragma unroll
    for (int u = 0; u < 16; u++) acc[u] = 0.0f;
    for (int j = 0; j < CHUNK; j++) {
        float kd = Ks[j * HD + d0];
#pragma unroll
        for (int u = 0; u < 16; u++) acc[u] += kd * Vs[j * HD + e0 + u];
    }
    float* out = g_KVc + ((size_t)h * NCHUNK + c) * (HD * HD) + d0 * HD + e0;
#pragma unroll
    for (int u = 0; u < 4; u++)
        ((float4*)out)[u] = make_float4(acc[4 * u], acc[4 * u + 1],
                                        acc[4 * u + 2], acc[4 * u + 3]);
    if (tid < HD) {
        double s0 = 0.0, s1 = 0.0;
        for (int j = 0; j < CHUNK; j += 2) {
            s0 += (double)Ks[j * HD + tid];
            s1 += (double)Ks[(j + 1) * HD + tid];
        }
        g_Ksc[((size_t)h * NCHUNK + c) * HD + tid] = s0 + s1;
    } else if (tid < 2 * HD) {
        int e = tid - HD;
        float s = 0.0f;
        for (int j = 0; j < CHUNK; j++) s += Vs[j * HD + e];
        g_Vsc[((size_t)h * NCHUNK + c) * HD + e] = s;
    }
}

// ---------------- per-chunk attention (ROUND-11 EXACT) ------------------
__global__ __launch_bounds__(256) void chunk_attn() {
    extern __shared__ char smraw[];
    double* KspD = (double*)smraw;            // [64]
    double* denD = KspD + HD;                 // [128]
    float* Qst = (float*)(denD + CHUNK);      // [64][128]
    float* Kst = Qst + HD * CHUNK;            // [64][128]
    float* Vs  = Kst + HD * CHUNK;            // [128][64]
    float* Sct = Vs + CHUNK * HD;             // [128][128]
    double* kcumD = (double*)Sct;             // aliased pre-scores
    float* KVp = Sct + CHUNK * CHUNK;         // [64][64]
    float* Vsp = KVp + HD * HD;               // [64]

    const int c = blockIdx.x, h = blockIdx.y, tid = threadIdx.x;
    const float* Qg = g_Q + ((size_t)h * T_SEQ + c * CHUNK) * HD;
    const float* Kg = g_K + ((size_t)h * T_SEQ + c * CHUNK) * HD;
    const float* Vg = g_V + ((size_t)h * T_SEQ + c * CHUNK) * HD;

    for (int it = tid; it < CHUNK * HD / 4; it += 256) {
        int t = it >> 4;
        int d4 = (it & 15) * 4;
        float4 q4 = ((const float4*)(Qg + t * HD))[it & 15];
        float4 k4 = ((const float4*)(Kg + t * HD))[it & 15];
        Qst[(d4 + 0) * CHUNK + t] = q4.x; Qst[(d4 + 1) * CHUNK + t] = q4.y;
        Qst[(d4 + 2) * CHUNK + t] = q4.z; Qst[(d4 + 3) * CHUNK + t] = q4.w;
        Kst[(d4 + 0) * CHUNK + t] = k4.x; Kst[(d4 + 1) * CHUNK + t] = k4.y;
        Kst[(d4 + 2) * CHUNK + t] = k4.z; Kst[(d4 + 3) * CHUNK + t] = k4.w;
        ((float4*)Vs)[it] = ((const float4*)Vg)[it];
    }

    {
        float kv[16];
#pragma unroll
        for (int u = 0; u < 16; u++) kv[u] = 0.0f;
        for (int cp = 0; cp < c; cp++) {
            const float* p = g_KVc + ((size_t)h * NCHUNK + cp) * (HD * HD) + tid * 16;
#pragma unroll
            for (int u = 0; u < 16; u++) kv[u] += p[u];
        }
#pragma unroll
        for (int u = 0; u < 16; u++) KVp[tid * 16 + u] = kv[u];
        if (tid < HD) {
            double s = 0.0;
            for (int cp = 0; cp < c; cp++)
                s += g_Ksc[((size_t)h * NCHUNK + cp) * HD + tid];
            KspD[tid] = s;
        } else if (tid < 2 * HD) {
            int e = tid - HD;
            float s = 0.0f;
            for (int cp = 0; cp < c; cp++)
                s += g_Vsc[((size_t)h * NCHUNK + cp) * HD + e];
            Vsp[e] = s;
        }
    }
    __syncthreads();

    if (tid < HD) {
        const int d = tid;
        double acc = KspD[d];
        for (int j = 0; j < CHUNK; j++) {
            acc += (double)Kst[d * CHUNK + j];
            kcumD[d * CHUNK + j] = acc;
        }
    }
    __syncthreads();

    if (tid < CHUNK) {
        const int i = tid;
        double s0 = (double)(c * CHUNK + i + 1), s1 = 0.0, s2 = 0.0, s3 = 0.0;
        for (int d = 0; d < HD; d += 4) {
            s0 += (double)Qst[(d + 0) * CHUNK + i] * kcumD[(d + 0) * CHUNK + i];
            s1 += (double)Qst[(d + 1) * CHUNK + i] * kcumD[(d + 1) * CHUNK + i];
            s2 += (double)Qst[(d + 2) * CHUNK + i] * kcumD[(d + 2) * CHUNK + i];
            s3 += (double)Qst[(d + 3) * CHUNK + i] * kcumD[(d + 3) * CHUNK + i];
        }
        denD[i] = (s0 + s1) + (s2 + s3);
    }
    __syncthreads();

    {
        const int tx = tid & 15;
        const int ty = tid >> 4;
        const int i0 = tx * 8, j0 = ty * 8;
        float acc[8][8];
#pragma unroll
        for (int jj = 0; jj < 8; jj++)
#pragma unroll
            for (int ii = 0; ii < 8; ii++) acc[jj][ii] = 1.0f;
        for (int d = 0; d < HD; d++) {
            float q[8], k[8];
            *(float4*)&q[0] = *(const float4*)&Qst[d * CHUNK + i0];
            *(float4*)&q[4] = *(const float4*)&Qst[d * CHUNK + i0 + 4];
            *(float4*)&k[0] = *(const float4*)&Kst[d * CHUNK + j0];
            *(float4*)&k[4] = *(const float4*)&Kst[d * CHUNK + j0 + 4];
#pragma unroll
            for (int jj = 0; jj < 8; jj++)
#pragma unroll
                for (int ii = 0; ii < 8; ii++) acc[jj][ii] += k[jj] * q[ii];
        }
        __syncthreads();
#pragma unroll
        for (int jj = 0; jj < 8; jj++) {
            int j = j0 + jj;
            float v[8];
#pragma unroll
            for (int ii = 0; ii < 8; ii++)
                v[ii] = (j <= i0 + ii) ? acc[jj][ii] : 0.0f;
            float4* sp = (float4*)&Sct[j * CHUNK + i0];
            sp[0] = make_float4(v[0], v[1], v[2], v[3]);
            sp[1] = make_float4(v[4], v[5], v[6], v[7]);
        }
    }
    __syncthreads();

    {
        const int ti = tid >> 3;
        const int i0 = ti * 4;
        const int e0 = (tid & 7) * 8;
        float acc[4][8];
#pragma unroll
        for (int ii = 0; ii < 4; ii++)
#pragma unroll
            for (int ee = 0; ee < 8; ee++) acc[ii][ee] = 0.0f;
        for (int d = 0; d < HD; d++) {
            float q[4], kv[8];
            *(float4*)&q[0] = *(const float4*)&Qst[d * CHUNK + i0];
            *(float4*)&kv[0] = *(const float4*)&KVp[d * HD + e0];
            *(float4*)&kv[4] = *(const float4*)&KVp[d * HD + e0 + 4];
#pragma unroll
            for (int ii = 0; ii < 4; ii++)
#pragma unroll
                for (int ee = 0; ee < 8; ee++) acc[ii][ee] += q[ii] * kv[ee];
        }
        for (int j = 0; j < CHUNK; j++) {
            float sv[4], v[8];
            *(float4*)&sv[0] = *(const float4*)&Sct[j * CHUNK + i0];
            *(float4*)&v[0] = *(const float4*)&Vs[j * HD + e0];
            *(float4*)&v[4] = *(const float4*)&Vs[j * HD + e0 + 4];
#pragma unroll
            for (int ii = 0; ii < 4; ii++)
#pragma unroll
                for (int ee = 0; ee < 8; ee++) acc[ii][ee] += sv[ii] * v[ee];
        }
#pragma unroll
        for (int ii = 0; ii < 4; ii++) {
            int i = i0 + ii;
            int t = c * CHUNK + i;
            double inv = 1.0 / denD[i];
            float o[8];
#pragma unroll
            for (int ee = 0; ee < 8; ee++)
                o[ee] = (float)((double)(acc[ii][ee] + Vsp[e0 + ee]) * inv);
            float4* yp = (float4*)(g_Y + (size_t)t * C_DIM + h * HD + e0);
            yp[0] = make_float4(o[0], o[1], o[2], o[3]);
            yp[1] = make_float4(o[4], o[5], o[6], o[7]);
        }
    }
}

// ---------------- launch ------------------------------------------------
extern "C" void kernel_launch(void* const* d_in, const int* in_sizes, int n_in,
                              void* d_out, int out_size) {
    const float* x      = (const float*)d_in[0];
    const float* w_attn = (const float*)d_in[1];
    const float* w_proj = (const float*)d_in[2];
    const float* cosb   = (const float*)d_in[3];
    const float* sinb   = (const float*)d_in[4];
    float* out = (float*)d_out;

    void *p_qk, *p_vt, *p_Y;
    cudaGetSymbolAddress(&p_qk, g_qk);
    cudaGetSymbolAddress(&p_vt, g_vt);
    cudaGetSymbolAddress(&p_Y, g_Y);

    int smem_gemm = 16384 * 4;
    int smem_sums = 2 * CHUNK * HD * (int)sizeof(float);
    int smem_attn = (int)(sizeof(double) * (HD + CHUNK)) +
                    (int)(sizeof(float) *
                          (3 * CHUNK * HD + CHUNK * CHUNK + HD * HD + HD));
    cudaFuncSetAttribute(gemm_mma3<0>, cudaFuncAttributeMaxDynamicSharedMemorySize,
                         smem_gemm);
    cudaFuncSetAttribute(gemm_mma3<1>, cudaFuncAttributeMaxDynamicSharedMemorySize,
                         smem_gemm);
    cudaFuncSetAttribute(chunk_sums, cudaFuncAttributeMaxDynamicSharedMemorySize,
                         smem_sums);
    cudaFuncSetAttribute(chunk_attn, cudaFuncAttributeMaxDynamicSharedMemorySize,
                         smem_attn);

    // 1a) q|k = x @ w_attn_qk^T  (SIMT fp32, bit-identical q/k path)
    sgemm_qk<<<dim3(QK_N / 128, T_SEQ / 128), 256>>>(
        x, w_attn, (float*)p_qk, T_SEQ, QK_N, C_DIM);
    // 1b) v = x @ w_attn_v^T     (tf32 mma, unamplified path)
    gemm_mma3<1><<<dim3(C_DIM / 128, T_SEQ / 128), 256, smem_gemm>>>(
        x, w_attn, (float*)p_vt, T_SEQ, C_DIM, C_DIM);
    // 2) rope + scatter
    rope_scatter2<<<(T_SEQ * NH * HD + 255) / 256, 256>>>(cosb, sinb);
    // 3) chunk sums
    chunk_sums<<<dim3(NCHUNK, NH), 256, smem_sums>>>();
    // 4) chunk attention (round-11 exact)
    chunk_attn<<<dim3(NCHUNK, NH), 256, smem_attn>>>();
    // 5) out = Y @ w_proj^T      (tf32 mma)
    gemm_mma3<0><<<dim3(C_DIM / 128, T_SEQ / 128), 256, smem_gemm>>>(
        (const float*)p_Y, w_proj, out, T_SEQ, C_DIM, C_DIM);
}

// round 14
// speedup vs baseline: 1.5880x; 1.0741x over previous
#include <cuda_runtime.h>
#include <cstdint>
#include <cstddef>

#define T_SEQ 2048
#define NH 16
#define HD 64
#define C_DIM 1024
#define QK_N 2048
#define CHUNK 128
#define NCHUNK (T_SEQ / CHUNK)

// ---------------- scratch (static __device__, no allocs) ----------------
__device__ float  g_qk[T_SEQ * QK_N];
__device__ float  g_vt[T_SEQ * C_DIM];
__device__ float  g_Q[NH * T_SEQ * HD];
__device__ float  g_K[NH * T_SEQ * HD];
__device__ float  g_V[NH * T_SEQ * HD];
__device__ float  g_KVc[NH * NCHUNK * HD * HD];
__device__ double g_Ksc[NH * NCHUNK * HD];
__device__ float  g_Vsc[NH * NCHUNK * HD];
__device__ float  g_S[NH * NCHUNK * CHUNK * CHUNK];   // 16.8MB scores
__device__ double g_den[NH * T_SEQ];                  // fp64 denominators
__device__ float  g_Y[T_SEQ * C_DIM];

// ====== SIMT fp32 NT GEMM, gathered-B for q/k (bit-identical math) ======
__global__ __launch_bounds__(256) void sgemm_qk(
    const float* __restrict__ A, const float* __restrict__ B,
    float* __restrict__ C, int M, int N, int K) {
    __shared__ float As[8][128];
    __shared__ float Bs[8][128];
    const int bm = blockIdx.y * 128;
    const int bn = blockIdx.x * 128;
    const int tid = threadIdx.x;
    const int tx = tid & 15;
    const int ty = tid >> 4;
    const int lr = tid >> 1;
    const int lk = (tid & 1) << 2;

    const int gb = bn + lr;
    const int brow = ((gb >> 7) * 192) + (gb & 127);
    const float* Ap = A + (size_t)(bm + lr) * K + lk;
    const float* Bp = B + (size_t)brow * K + lk;

    float acc[8][8];
#pragma unroll
    for (int i = 0; i < 8; i++)
#pragma unroll
        for (int j = 0; j < 8; j++) acc[i][j] = 0.0f;

    for (int k0 = 0; k0 < K; k0 += 8) {
        float4 a4 = *(const float4*)(Ap + k0);
        float4 b4 = *(const float4*)(Bp + k0);
        As[lk + 0][lr] = a4.x; As[lk + 1][lr] = a4.y;
        As[lk + 2][lr] = a4.z; As[lk + 3][lr] = a4.w;
        Bs[lk + 0][lr] = b4.x; Bs[lk + 1][lr] = b4.y;
        Bs[lk + 2][lr] = b4.z; Bs[lk + 3][lr] = b4.w;
        __syncthreads();
#pragma unroll
        for (int kk = 0; kk < 8; kk++) {
            float a[8], b[8];
            *(float4*)&a[0] = *(const float4*)&As[kk][ty * 8];
            *(float4*)&a[4] = *(const float4*)&As[kk][ty * 8 + 4];
            *(float4*)&b[0] = *(const float4*)&Bs[kk][tx * 8];
            *(float4*)&b[4] = *(const float4*)&Bs[kk][tx * 8 + 4];
#pragma unroll
            for (int i = 0; i < 8; i++)
#pragma unroll
                for (int j = 0; j < 8; j++) acc[i][j] += a[i] * b[j];
        }
        __syncthreads();
    }
#pragma unroll
    for (int i = 0; i < 8; i++) {
        float4* cp = (float4*)(C + (size_t)(bm + ty * 8 + i) * N + bn + tx * 8);
        cp[0] = make_float4(acc[i][0], acc[i][1], acc[i][2], acc[i][3]);
        cp[1] = make_float4(acc[i][4], acc[i][5], acc[i][6], acc[i][7]);
    }
}

// =================== tf32 mma.sync helpers (sm_80+ PTX) =================
__device__ __forceinline__ void split2(float x, uint32_t& h, uint32_t& l) {
    asm("cvt.rna.tf32.f32 %0, %1;" : "=r"(h) : "f"(x));
    float r = x - __uint_as_float(h);
    asm("cvt.rna.tf32.f32 %0, %1;" : "=r"(l) : "f"(r));
}

__device__ __forceinline__ void mma_tf32(float* d, const uint32_t* a,
                                         const uint32_t* b) {
    asm volatile(
        "mma.sync.aligned.m16n8k8.row.col.f32.tf32.tf32.f32 "
        "{%0,%1,%2,%3}, {%4,%5,%6,%7}, {%8,%9}, {%0,%1,%2,%3};"
        : "+f"(d[0]), "+f"(d[1]), "+f"(d[2]), "+f"(d[3])
        : "r"(a[0]), "r"(a[1]), "r"(a[2]), "r"(a[3]), "r"(b[0]), "r"(b[1]));
}

#define CP_ASYNC16(dst, src) \
    asm volatile("cp.async.cg.shared.global [%0], [%1], 16;" \
                 :: "r"(dst), "l"(src))
#define CP_COMMIT() asm volatile("cp.async.commit_group;" ::: "memory")
#define CP_WAIT1()  asm volatile("cp.async.wait_group 1;" ::: "memory")
#define CP_WAIT0()  asm volatile("cp.async.wait_group 0;" ::: "memory")

// ======= tf32 mma NT GEMM (3-product).  REMAP=1: B row gathered for v ===
template <int REMAP>
__global__ __launch_bounds__(256, 1) void gemm_mma3(
    const float* __restrict__ A, const float* __restrict__ B,
    float* __restrict__ C, int M, int N, int K) {
    extern __shared__ float smf[];
    float* As = smf;
    float* Bs = smf + 8192;
    const uint32_t smA_u32 = (uint32_t)__cvta_generic_to_shared(As);
    const uint32_t smB_u32 = (uint32_t)__cvta_generic_to_shared(Bs);

    const int tid = threadIdx.x;
    const int wid = tid >> 5;
    const int lane = tid & 31;
    const int bm = blockIdx.y * 128;
    const int bn = blockIdx.x * 128;
    const int warpM = (wid >> 2) * 64;
    const int warpN = (wid & 3) * 32;
    const int nk = K >> 5;

    const int lr = tid >> 1;
    const int j0 = (tid & 1) * 4;
    const int lrx = lr & 7;
    const int gb = bn + lr;
    const int brow = REMAP ? (((gb >> 6) * 192) + 128 + (gb & 63)) : gb;
    const float* Asrc = A + (size_t)(bm + lr) * K;
    const float* Bsrc = B + (size_t)brow * K;

    float acc[4][4][4];
#pragma unroll
    for (int mt = 0; mt < 4; mt++)
#pragma unroll
        for (int nt = 0; nt < 4; nt++)
#pragma unroll
            for (int u = 0; u < 4; u++) acc[mt][nt][u] = 0.0f;

    {
        const uint32_t ab = smA_u32 + lr * 128;
        const uint32_t bb = smB_u32 + lr * 128;
#pragma unroll
        for (int j = 0; j < 4; j++) {
            int c4 = j0 + j;
            int swc = (c4 ^ lrx) * 16;
            CP_ASYNC16(ab + swc, Asrc + c4 * 4);
            CP_ASYNC16(bb + swc, Bsrc + c4 * 4);
        }
        CP_COMMIT();
    }

    for (int it = 0; it < nk; it++) {
        if (it + 1 < nk) {
            const int nb = (it + 1) & 1;
            const int kblk = (it + 1) << 5;
            const uint32_t ab = smA_u32 + nb * 16384 + lr * 128;
            const uint32_t bb = smB_u32 + nb * 16384 + lr * 128;
#pragma unroll
            for (int j = 0; j < 4; j++) {
                int c4 = j0 + j;
                int swc = (c4 ^ lrx) * 16;
                CP_ASYNC16(ab + swc, Asrc + kblk + c4 * 4);
                CP_ASYNC16(bb + swc, Bsrc + kblk + c4 * 4);
            }
            CP_COMMIT();
            CP_WAIT1();
        } else {
            CP_WAIT0();
        }
        __syncthreads();

        const float* Ab = As + (it & 1) * 4096;
        const float* Bb = Bs + (it & 1) * 4096;
#pragma unroll
        for (int ks = 0; ks < 4; ks++) {
            uint32_t bh[4][2], bl[4][2];
#pragma unroll
            for (int nt = 0; nt < 4; nt++) {
                int n0 = warpN + nt * 8 + (lane >> 2);
                const float* bp = Bb + n0 * 32;
                int s0 = ((2 * ks) ^ (n0 & 7)) * 4 + (lane & 3);
                int s1 = ((2 * ks + 1) ^ (n0 & 7)) * 4 + (lane & 3);
                split2(bp[s0], bh[nt][0], bl[nt][0]);
                split2(bp[s1], bh[nt][1], bl[nt][1]);
            }
#pragma unroll
            for (int mt = 0; mt < 4; mt++) {
                int r0 = warpM + mt * 16 + (lane >> 2);
                const float* ap0 = Ab + r0 * 32;
                const float* ap1 = ap0 + 8 * 32;
                int s0 = ((2 * ks) ^ (r0 & 7)) * 4 + (lane & 3);
                int s1 = ((2 * ks + 1) ^ (r0 & 7)) * 4 + (lane & 3);
                uint32_t ah[4], al[4];
                split2(ap0[s0], ah[0], al[0]);
                split2(ap1[s0], ah[1], al[1]);
                split2(ap0[s1], ah[2], al[2]);
                split2(ap1[s1], ah[3], al[3]);
#pragma unroll
                for (int nt = 0; nt < 4; nt++) {
                    mma_tf32(acc[mt][nt], ah, bh[nt]);
                    mma_tf32(acc[mt][nt], ah, bl[nt]);
                    mma_tf32(acc[mt][nt], al, bh[nt]);
                }
            }
        }
        __syncthreads();
    }

#pragma unroll
    for (int mt = 0; mt < 4; mt++) {
        int r0 = bm + warpM + mt * 16 + (lane >> 2);
#pragma unroll
        for (int nt = 0; nt < 4; nt++) {
            int cc = bn + warpN + nt * 8 + 2 * (lane & 3);
            *(float2*)(C + (size_t)r0 * N + cc) =
                make_float2(acc[mt][nt][0], acc[mt][nt][1]);
            *(float2*)(C + (size_t)(r0 + 8) * N + cc) =
                make_float2(acc[mt][nt][2], acc[mt][nt][3]);
        }
    }
}

// ---------------- RoPE + scatter to head-major Q/K/V --------------------
__global__ __launch_bounds__(256) void rope_scatter2(
    const float* __restrict__ cosb, const float* __restrict__ sinb) {
    int tid = blockIdx.x * blockDim.x + threadIdx.x;
    if (tid >= T_SEQ * NH * HD) return;
    int d = tid & 63;
    int h = (tid >> 6) & 15;
    int t = tid >> 10;
    const float* row = g_qk + (size_t)t * QK_N + h * 128;
    float c = cosb[t * HD + d];
    float s = sinb[t * HD + d];
    int pd = (d < 32) ? d + 32 : d - 32;
    float sgn = (d < 32) ? -1.0f : 1.0f;

    float q = row[d];
    float qr = sgn * row[pd];
    float k = row[64 + d];
    float kr = sgn * row[64 + pd];
    size_t o = ((size_t)h * T_SEQ + t) * HD + d;
    g_Q[o] = q * c + qr * s;
    g_K[o] = k * c + kr * s;
    g_V[o] = g_vt[(size_t)t * C_DIM + h * HD + d];
}

// ---------------- per-chunk sums: KV outer, Ksum(fp64), Vsum ------------
// Register-blocked: d-pair x e-group-of-8.  Per-element j-chains identical
// to previous version -> KVc/Ksc/Vsc bit-identical.
__global__ __launch_bounds__(256) void chunk_sums() {
    extern __shared__ float smf2[];
    float* Ks = smf2;
    float* Vs = smf2 + CHUNK * HD;
    const int c = blockIdx.x, h = blockIdx.y, tid = threadIdx.x;
    const float* Kg = g_K + ((size_t)h * T_SEQ + c * CHUNK) * HD;
    const float* Vg = g_V + ((size_t)h * T_SEQ + c * CHUNK) * HD;
    for (int it = tid; it < CHUNK * HD / 4; it += 256) {
        ((float4*)Ks)[it] = ((const float4*)Kg)[it];
        ((float4*)Vs)[it] = ((const float4*)Vg)[it];
    }
    __syncthreads();

    const int d0 = (tid >> 3) << 1;      // 0,2,...,62
    const int e0 = (tid & 7) * 8;        // 0,8,...,56
    float acc0[8], acc1[8];
#pragma unroll
    for (int u = 0; u < 8; u++) { acc0[u] = 0.0f; acc1[u] = 0.0f; }
    for (int j = 0; j < CHUNK; j++) {
        float2 kk = *(const float2*)&Ks[j * HD + d0];
        float v[8];
        *(float4*)&v[0] = *(const float4*)&Vs[j * HD + e0];
        *(float4*)&v[4] = *(const float4*)&Vs[j * HD + e0 + 4];
#pragma unroll
        for (int u = 0; u < 8; u++) {
            acc0[u] += kk.x * v[u];
            acc1[u] += kk.y * v[u];
        }
    }
    float* out = g_KVc + ((size_t)h * NCHUNK + c) * (HD * HD);
    *(float4*)&out[(d0 + 0) * HD + e0]     = make_float4(acc0[0], acc0[1], acc0[2], acc0[3]);
    *(float4*)&out[(d0 + 0) * HD + e0 + 4] = make_float4(acc0[4], acc0[5], acc0[6], acc0[7]);
    *(float4*)&out[(d0 + 1) * HD + e0]     = make_float4(acc1[0], acc1[1], acc1[2], acc1[3]);
    *(float4*)&out[(d0 + 1) * HD + e0 + 4] = make_float4(acc1[4], acc1[5], acc1[6], acc1[7]);

    if (tid < HD) {
        double s0 = 0.0, s1 = 0.0;
        for (int j = 0; j < CHUNK; j += 2) {
            s0 += (double)Ks[j * HD + tid];
            s1 += (double)Ks[(j + 1) * HD + tid];
        }
        g_Ksc[((size_t)h * NCHUNK + c) * HD + tid] = s0 + s1;
    } else if (tid < 2 * HD) {
        int e = tid - HD;
        float s = 0.0f;
        for (int j = 0; j < CHUNK; j++) s += Vs[j * HD + e];
        g_Vsc[((size_t)h * NCHUNK + c) * HD + e] = s;
    }
}

// ---------------- chunk_score: scores -> g_S, fp64 den -> g_den ---------
// smem 96.5KB -> 2 CTAs/SM.  kcum processed in two j-halves of 32KB; all
// fp64 chains keep the exact order of the monolithic version.
__global__ __launch_bounds__(256, 2) void chunk_score() {
    extern __shared__ char smraw[];
    double* KspD  = (double*)smraw;                  // [64]
    double* kcumH = (double*)(smraw + 512);          // [64][64] (one j-half)
    float* Qst = (float*)(smraw + 512 + 32768);      // [64][128] d-major
    float* Kst = Qst + HD * CHUNK;                   // [64][128]

    const int c = blockIdx.x, h = blockIdx.y, tid = threadIdx.x;
    const float* Qg = g_Q + ((size_t)h * T_SEQ + c * CHUNK) * HD;
    const float* Kg = g_K + ((size_t)h * T_SEQ + c * CHUNK) * HD;

    for (int it = tid; it < CHUNK * HD / 4; it += 256) {
        int t = it >> 4;
        int d4 = (it & 15) * 4;
        float4 q4 = ((const float4*)(Qg + t * HD))[it & 15];
        float4 k4 = ((const float4*)(Kg + t * HD))[it & 15];
        Qst[(d4 + 0) * CHUNK + t] = q4.x; Qst[(d4 + 1) * CHUNK + t] = q4.y;
        Qst[(d4 + 2) * CHUNK + t] = q4.z; Qst[(d4 + 3) * CHUNK + t] = q4.w;
        Kst[(d4 + 0) * CHUNK + t] = k4.x; Kst[(d4 + 1) * CHUNK + t] = k4.y;
        Kst[(d4 + 2) * CHUNK + t] = k4.z; Kst[(d4 + 3) * CHUNK + t] = k4.w;
    }
    if (tid < HD) {
        double s = 0.0;
        for (int cp = 0; cp < c; cp++)
            s += g_Ksc[((size_t)h * NCHUNK + cp) * HD + tid];
        KspD[tid] = s;
    }
    __syncthreads();

#pragma unroll 1
    for (int half = 0; half < 2; half++) {
        if (tid < HD) {
            const int d = tid;
            double acc = KspD[d];
            for (int jj = 0; jj < 64; jj++) {
                acc += (double)Kst[d * CHUNK + half * 64 + jj];
                kcumH[d * 64 + jj] = acc;
            }
            KspD[d] = acc;   // carry for next half
        }
        __syncthreads();
        if (tid < 64) {
            const int il = tid;
            const int i = half * 64 + il;
            double s0 = (double)(c * CHUNK + i + 1), s1 = 0.0, s2 = 0.0, s3 = 0.0;
            for (int d = 0; d < HD; d += 4) {
                s0 += (double)Qst[(d + 0) * CHUNK + i] * kcumH[(d + 0) * 64 + il];
                s1 += (double)Qst[(d + 1) * CHUNK + i] * kcumH[(d + 1) * 64 + il];
                s2 += (double)Qst[(d + 2) * CHUNK + i] * kcumH[(d + 2) * 64 + il];
                s3 += (double)Qst[(d + 3) * CHUNK + i] * kcumH[(d + 3) * 64 + il];
            }
            g_den[(size_t)h * T_SEQ + c * CHUNK + i] = (s0 + s1) + (s2 + s3);
        }
        __syncthreads();
    }

    // scores: S[j][i] = (j<=i) ? 1 + q_i . k_j : 0  (8x8 tiles, to global)
    {
        float* Sg = g_S + ((size_t)h * NCHUNK + c) * (CHUNK * CHUNK);
        const int tx = tid & 15;
        const int ty = tid >> 4;
        const int i0 = tx * 8, j0 = ty * 8;
        float acc[8][8];
#pragma unroll
        for (int jj = 0; jj < 8; jj++)
#pragma unroll
            for (int ii = 0; ii < 8; ii++) acc[jj][ii] = 1.0f;
        for (int d = 0; d < HD; d++) {
            float q[8], k[8];
            *(float4*)&q[0] = *(const float4*)&Qst[d * CHUNK + i0];
            *(float4*)&q[4] = *(const float4*)&Qst[d * CHUNK + i0 + 4];
            *(float4*)&k[0] = *(const float4*)&Kst[d * CHUNK + j0];
            *(float4*)&k[4] = *(const float4*)&Kst[d * CHUNK + j0 + 4];
#pragma unroll
            for (int jj = 0; jj < 8; jj++)
#pragma unroll
                for (int ii = 0; ii < 8; ii++) acc[jj][ii] += k[jj] * q[ii];
        }
#pragma unroll
        for (int jj = 0; jj < 8; jj++) {
            int j = j0 + jj;
            float v[8];
#pragma unroll
            for (int ii = 0; ii < 8; ii++)
                v[ii] = (j <= i0 + ii) ? acc[jj][ii] : 0.0f;
            float4* sp = (float4*)&Sg[j * CHUNK + i0];
            sp[0] = make_float4(v[0], v[1], v[2], v[3]);
            sp[1] = make_float4(v[4], v[5], v[6], v[7]);
        }
    }
}

// ---------------- chunk_out: numerators + divide ------------------------
// smem 112KB exactly -> 2 CTAs/SM.  Same tiling/order as monolith.
__global__ __launch_bounds__(256, 2) void chunk_out() {
    extern __shared__ char smraw[];
    float* Sct = (float*)smraw;               // [128][128]
    float* Vs  = Sct + CHUNK * CHUNK;         // [128][64]
    float* KVp = Vs + CHUNK * HD;             // [64][64]

    const int c = blockIdx.x, h = blockIdx.y, tid = threadIdx.x;
    const float* Sg = g_S + ((size_t)h * NCHUNK + c) * (CHUNK * CHUNK);
    const float* Vg = g_V + ((size_t)h * T_SEQ + c * CHUNK) * HD;

    for (int it = tid; it < CHUNK * CHUNK / 4; it += 256)
        ((float4*)Sct)[it] = ((const float4*)Sg)[it];
    for (int it = tid; it < CHUNK * HD / 4; it += 256)
        ((float4*)Vs)[it] = ((const float4*)Vg)[it];

    // prefix KV state (same order as before)
    {
        float kv[16];
#pragma unroll
        for (int u = 0; u < 16; u++) kv[u] = 0.0f;
        for (int cp = 0; cp < c; cp++) {
            const float* p = g_KVc + ((size_t)h * NCHUNK + cp) * (HD * HD) + tid * 16;
#pragma unroll
            for (int u = 0; u < 16; u++) kv[u] += p[u];
        }
#pragma unroll
        for (int u = 0; u < 16; u++) KVp[tid * 16 + u] = kv[u];
    }
    __syncthreads();

    {
        const int ti = tid >> 3;
        const int i0 = ti * 4;
        const int e0 = (tid & 7) * 8;

        // Vsp in registers (same ascending-cp order as before)
        float vsp[8];
#pragma unroll
        for (int u = 0; u < 8; u++) vsp[u] = 0.0f;
        for (int cp = 0; cp < c; cp++) {
            const float* p = g_Vsc + ((size_t)h * NCHUNK + cp) * HD + e0;
#pragma unroll
            for (int u = 0; u < 8; u++) vsp[u] += p[u];
        }

        float acc[4][8];
#pragma unroll
        for (int ii = 0; ii < 4; ii++)
#pragma unroll
            for (int ee = 0; ee < 8; ee++) acc[ii][ee] = 0.0f;
        // NOTE: prefix (q.KVp) part needs Qst d-major reads; read q from
        // global instead: q[i0+ii][d].  Keep identical accumulation order:
        // first the d-loop (q*KVp), then the j-loop (s*v).
        const float* Qg = g_Q + ((size_t)h * T_SEQ + c * CHUNK) * HD;
        for (int d = 0; d < HD; d++) {
            float q[4], kv[8];
            q[0] = Qg[(i0 + 0) * HD + d];
            q[1] = Qg[(i0 + 1) * HD + d];
            q[2] = Qg[(i0 + 2) * HD + d];
            q[3] = Qg[(i0 + 3) * HD + d];
            *(float4*)&kv[0] = *(const float4*)&KVp[d * HD + e0];
            *(float4*)&kv[4] = *(const float4*)&KVp[d * HD + e0 + 4];
#pragma unroll
            for (int ii = 0; ii < 4; ii++)
#pragma unroll
                for (int ee = 0; ee < 8; ee++) acc[ii][ee] += q[ii] * kv[ee];
        }
        for (int j = 0; j < CHUNK; j++) {
            float sv[4], v[8];
            *(float4*)&sv[0] = *(const float4*)&Sct[j * CHUNK + i0];
            *(float4*)&v[0] = *(const float4*)&Vs[j * HD + e0];
            *(float4*)&v[4] = *(const float4*)&Vs[j * HD + e0 + 4];
#pragma unroll
            for (int ii = 0; ii < 4; ii++)
#pragma unroll
                for (int ee = 0; ee < 8; ee++) acc[ii][ee] += sv[ii] * v[ee];
        }
#pragma unroll
        for (int ii = 0; ii < 4; ii++) {
            int i = i0 + ii;
            int t = c * CHUNK + i;
            double inv = 1.0 / g_den[(size_t)h * T_SEQ + c * CHUNK + i];
            float o[8];
#pragma unroll
            for (int ee = 0; ee < 8; ee++)
                o[ee] = (float)((double)(acc[ii][ee] + vsp[ee]) * inv);
            float4* yp = (float4*)(g_Y + (size_t)t * C_DIM + h * HD + e0);
            yp[0] = make_float4(o[0], o[1], o[2], o[3]);
            yp[1] = make_float4(o[4], o[5], o[6], o[7]);
        }
    }
}

// ---------------- launch ------------------------------------------------
extern "C" void kernel_launch(void* const* d_in, const int* in_sizes, int n_in,
                              void* d_out, int out_size) {
    const float* x      = (const float*)d_in[0];
    const float* w_attn = (const float*)d_in[1];
    const float* w_proj = (const float*)d_in[2];
    const float* cosb   = (const float*)d_in[3];
    const float* sinb   = (const float*)d_in[4];
    float* out = (float*)d_out;

    void *p_qk, *p_vt, *p_Y;
    cudaGetSymbolAddress(&p_qk, g_qk);
    cudaGetSymbolAddress(&p_vt, g_vt);
    cudaGetSymbolAddress(&p_Y, g_Y);

    int smem_gemm  = 16384 * 4;
    int smem_sums  = 2 * CHUNK * HD * (int)sizeof(float);          // 64K
    int smem_score = 512 + 32768 + 32768 + 32768;                  // 98816
    int smem_out   = (CHUNK * CHUNK + CHUNK * HD + HD * HD)
                     * (int)sizeof(float);                         // 114688
    cudaFuncSetAttribute(gemm_mma3<0>, cudaFuncAttributeMaxDynamicSharedMemorySize,
                         smem_gemm);
    cudaFuncSetAttribute(gemm_mma3<1>, cudaFuncAttributeMaxDynamicSharedMemorySize,
                         smem_gemm);
    cudaFuncSetAttribute(chunk_sums, cudaFuncAttributeMaxDynamicSharedMemorySize,
                         smem_sums);
    cudaFuncSetAttribute(chunk_score, cudaFuncAttributeMaxDynamicSharedMemorySize,
                         smem_score);
    cudaFuncSetAttribute(chunk_out, cudaFuncAttributeMaxDynamicSharedMemorySize,
                         smem_out);

    // 1a) q|k = x @ w_attn_qk^T  (SIMT fp32, bit-identical q/k path)
    sgemm_qk<<<dim3(QK_N / 128, T_SEQ / 128), 256>>>(
        x, w_attn, (float*)p_qk, T_SEQ, QK_N, C_DIM);
    // 1b) v = x @ w_attn_v^T     (tf32 mma, unamplified path)
    gemm_mma3<1><<<dim3(C_DIM / 128, T_SEQ / 128), 256, smem_gemm>>>(
        x, w_attn, (float*)p_vt, T_SEQ, C_DIM, C_DIM);
    // 2) rope + scatter
    rope_scatter2<<<(T_SEQ * NH * HD + 255) / 256, 256>>>(cosb, sinb);
    // 3) chunk sums
    chunk_sums<<<dim3(NCHUNK, NH), 256, smem_sums>>>();
    // 4a) scores + fp64 denominators
    chunk_score<<<dim3(NCHUNK, NH), 256, smem_score>>>();
    // 4b) numerators + divide
    chunk_out<<<dim3(NCHUNK, NH), 256, smem_out>>>();
    // 5) out = Y @ w_proj^T      (tf32 mma)
    gemm_mma3<0><<<dim3(C_DIM / 128, T_SEQ / 128), 256, smem_gemm>>>(
        (const float*)p_Y, w_proj, out, T_SEQ, C_DIM, C_DIM);
}

// round 16
// speedup vs baseline: 1.5939x; 1.0037x over previous
#include <cuda_runtime.h>
#include <cstdint>
#include <cstddef>

#define T_SEQ 2048
#define NH 16
#define HD 64
#define C_DIM 1024
#define QK_N 2048
#define CHUNK 128
#define NCHUNK (T_SEQ / CHUNK)

// ---------------- scratch (static __device__, no allocs) ----------------
__device__ float  g_qk[T_SEQ * QK_N];
__device__ float  g_vt[T_SEQ * C_DIM];
__device__ float  g_Q[NH * T_SEQ * HD];
__device__ float  g_K[NH * T_SEQ * HD];
__device__ float  g_V[NH * T_SEQ * HD];
__device__ float  g_KVc[NH * NCHUNK * HD * HD];
__device__ double g_Ksc[NH * NCHUNK * HD];
__device__ float  g_Vsc[NH * NCHUNK * HD];
__device__ float  g_S[NH * NCHUNK * CHUNK * CHUNK];   // 16.8MB scores
__device__ double g_den[NH * T_SEQ];                  // fp64 denominators
__device__ float  g_Y[T_SEQ * C_DIM];

// ====== SIMT fp32 NT GEMM (q/k), FFMA2 via fma.rn.f32x2 =================
// Same tiling/order as the proven SIMT kernel; each packed lane-pair holds
// two independent j-accumulators, so per-element math is bit-identical.
__global__ __launch_bounds__(256, 1) void sgemm_qk(
    const float* __restrict__ A, const float* __restrict__ B,
    float* __restrict__ C, int M, int N, int K) {
    __shared__ float As[8][128];
    __shared__ float Bs[8][128];
    const int bm = blockIdx.y * 128;
    const int bn = blockIdx.x * 128;
    const int tid = threadIdx.x;
    const int tx = tid & 15;
    const int ty = tid >> 4;
    const int lr = tid >> 1;
    const int lk = (tid & 1) << 2;

    const int gb = bn + lr;
    const int brow = ((gb >> 7) * 192) + (gb & 127);
    const float* Ap = A + (size_t)(bm + lr) * K + lk;
    const float* Bp = B + (size_t)brow * K + lk;

    unsigned long long acc2[8][4];   // packed {acc[i][2jp], acc[i][2jp+1]}
#pragma unroll
    for (int i = 0; i < 8; i++)
#pragma unroll
        for (int jp = 0; jp < 4; jp++) acc2[i][jp] = 0ull;  // {0.0f, 0.0f}

    for (int k0 = 0; k0 < K; k0 += 8) {
        float4 a4 = *(const float4*)(Ap + k0);
        float4 b4 = *(const float4*)(Bp + k0);
        As[lk + 0][lr] = a4.x; As[lk + 1][lr] = a4.y;
        As[lk + 2][lr] = a4.z; As[lk + 3][lr] = a4.w;
        Bs[lk + 0][lr] = b4.x; Bs[lk + 1][lr] = b4.y;
        Bs[lk + 2][lr] = b4.z; Bs[lk + 3][lr] = b4.w;
        __syncthreads();
#pragma unroll
        for (int kk = 0; kk < 8; kk++) {
            float a[8];
            *(float4*)&a[0] = *(const float4*)&As[kk][ty * 8];
            *(float4*)&a[4] = *(const float4*)&As[kk][ty * 8 + 4];
            unsigned long long b2[4];
            {
                ulonglong2 p0 = *(const ulonglong2*)&Bs[kk][tx * 8];
                ulonglong2 p1 = *(const ulonglong2*)&Bs[kk][tx * 8 + 4];
                b2[0] = p0.x; b2[1] = p0.y; b2[2] = p1.x; b2[3] = p1.y;
            }
            unsigned long long a2[8];
#pragma unroll
            for (int i = 0; i < 8; i++)
                asm("mov.b64 %0, {%1, %1};" : "=l"(a2[i]) : "f"(a[i]));
#pragma unroll
            for (int i = 0; i < 8; i++)
#pragma unroll
                for (int jp = 0; jp < 4; jp++)
                    asm("fma.rn.f32x2 %0, %1, %2, %0;"
                        : "+l"(acc2[i][jp]) : "l"(a2[i]), "l"(b2[jp]));
        }
        __syncthreads();
    }
#pragma unroll
    for (int i = 0; i < 8; i++) {
        float o[8];
#pragma unroll
        for (int jp = 0; jp < 4; jp++)
            asm("mov.b64 {%0, %1}, %2;"
                : "=f"(o[2 * jp]), "=f"(o[2 * jp + 1]) : "l"(acc2[i][jp]));
        float4* cp = (float4*)(C + (size_t)(bm + ty * 8 + i) * N + bn + tx * 8);
        cp[0] = make_float4(o[0], o[1], o[2], o[3]);
        cp[1] = make_float4(o[4], o[5], o[6], o[7]);
    }
}

// =================== tf32 mma.sync helpers (sm_80+ PTX) =================
__device__ __forceinline__ void split2(float x, uint32_t& h, uint32_t& l) {
    asm("cvt.rna.tf32.f32 %0, %1;" : "=r"(h) : "f"(x));
    float r = x - __uint_as_float(h);
    asm("cvt.rna.tf32.f32 %0, %1;" : "=r"(l) : "f"(r));
}

__device__ __forceinline__ void mma_tf32(float* d, const uint32_t* a,
                                         const uint32_t* b) {
    asm volatile(
        "mma.sync.aligned.m16n8k8.row.col.f32.tf32.tf32.f32 "
        "{%0,%1,%2,%3}, {%4,%5,%6,%7}, {%8,%9}, {%0,%1,%2,%3};"
        : "+f"(d[0]), "+f"(d[1]), "+f"(d[2]), "+f"(d[3])
        : "r"(a[0]), "r"(a[1]), "r"(a[2]), "r"(a[3]), "r"(b[0]), "r"(b[1]));
}

#define CP_ASYNC16(dst, src) \
    asm volatile("cp.async.cg.shared.global [%0], [%1], 16;" \
                 :: "r"(dst), "l"(src))
#define CP_COMMIT() asm volatile("cp.async.commit_group;" ::: "memory")
#define CP_WAIT1()  asm volatile("cp.async.wait_group 1;" ::: "memory")
#define CP_WAIT0()  asm volatile("cp.async.wait_group 0;" ::: "memory")

// ======= tf32 mma NT GEMM (3-product).  REMAP=1: B row gathered for v ===
template <int REMAP>
__global__ __launch_bounds__(256, 1) void gemm_mma3(
    const float* __restrict__ A, const float* __restrict__ B,
    float* __restrict__ C, int M, int N, int K) {
    extern __shared__ float smf[];
    float* As = smf;
    float* Bs = smf + 8192;
    const uint32_t smA_u32 = (uint32_t)__cvta_generic_to_shared(As);
    const uint32_t smB_u32 = (uint32_t)__cvta_generic_to_shared(Bs);

    const int tid = threadIdx.x;
    const int wid = tid >> 5;
    const int lane = tid & 31;
    const int bm = blockIdx.y * 128;
    const int bn = blockIdx.x * 128;
    const int warpM = (wid >> 2) * 64;
    const int warpN = (wid & 3) * 32;
    const int nk = K >> 5;

    const int lr = tid >> 1;
    const int j0 = (tid & 1) * 4;
    const int lrx = lr & 7;
    const int gb = bn + lr;
    const int brow = REMAP ? (((gb >> 6) * 192) + 128 + (gb & 63)) : gb;
    const float* Asrc = A + (size_t)(bm + lr) * K;
    const float* Bsrc = B + (size_t)brow * K;

    float acc[4][4][4];
#pragma unroll
    for (int mt = 0; mt < 4; mt++)
#pragma unroll
        for (int nt = 0; nt < 4; nt++)
#pragma unroll
            for (int u = 0; u < 4; u++) acc[mt][nt][u] = 0.0f;

    {
        const uint32_t ab = smA_u32 + lr * 128;
        const uint32_t bb = smB_u32 + lr * 128;
#pragma unroll
        for (int j = 0; j < 4; j++) {
            int c4 = j0 + j;
            int swc = (c4 ^ lrx) * 16;
            CP_ASYNC16(ab + swc, Asrc + c4 * 4);
            CP_ASYNC16(bb + swc, Bsrc + c4 * 4);
        }
        CP_COMMIT();
    }

    for (int it = 0; it < nk; it++) {
        if (it + 1 < nk) {
            const int nb = (it + 1) & 1;
            const int kblk = (it + 1) << 5;
            const uint32_t ab = smA_u32 + nb * 16384 + lr * 128;
            const uint32_t bb = smB_u32 + nb * 16384 + lr * 128;
#pragma unroll
            for (int j = 0; j < 4; j++) {
                int c4 = j0 + j;
                int swc = (c4 ^ lrx) * 16;
                CP_ASYNC16(ab + swc, Asrc + kblk + c4 * 4);
                CP_ASYNC16(bb + swc, Bsrc + kblk + c4 * 4);
            }
            CP_COMMIT();
            CP_WAIT1();
        } else {
            CP_WAIT0();
        }
        __syncthreads();

        const float* Ab = As + (it & 1) * 4096;
        const float* Bb = Bs + (it & 1) * 4096;
#pragma unroll
        for (int ks = 0; ks < 4; ks++) {
            uint32_t bh[4][2], bl[4][2];
#pragma unroll
            for (int nt = 0; nt < 4; nt++) {
                int n0 = warpN + nt * 8 + (lane >> 2);
                const float* bp = Bb + n0 * 32;
                int s0 = ((2 * ks) ^ (n0 & 7)) * 4 + (lane & 3);
                int s1 = ((2 * ks + 1) ^ (n0 & 7)) * 4 + (lane & 3);
                split2(bp[s0], bh[nt][0], bl[nt][0]);
                split2(bp[s1], bh[nt][1], bl[nt][1]);
            }
#pragma unroll
            for (int mt = 0; mt < 4; mt++) {
                int r0 = warpM + mt * 16 + (lane >> 2);
                const float* ap0 = Ab + r0 * 32;
                const float* ap1 = ap0 + 8 * 32;
                int s0 = ((2 * ks) ^ (r0 & 7)) * 4 + (lane & 3);
                int s1 = ((2 * ks + 1) ^ (r0 & 7)) * 4 + (lane & 3);
                uint32_t ah[4], al[4];
                split2(ap0[s0], ah[0], al[0]);
                split2(ap1[s0], ah[1], al[1]);
                split2(ap0[s1], ah[2], al[2]);
                split2(ap1[s1], ah[3], al[3]);
#pragma unroll
                for (int nt = 0; nt < 4; nt++) {
                    mma_tf32(acc[mt][nt], ah, bh[nt]);
                    mma_tf32(acc[mt][nt], ah, bl[nt]);
                    mma_tf32(acc[mt][nt], al, bh[nt]);
                }
            }
        }
        __syncthreads();
    }

#pragma unroll
    for (int mt = 0; mt < 4; mt++) {
        int r0 = bm + warpM + mt * 16 + (lane >> 2);
#pragma unroll
        for (int nt = 0; nt < 4; nt++) {
            int cc = bn + warpN + nt * 8 + 2 * (lane & 3);
            *(float2*)(C + (size_t)r0 * N + cc) =
                make_float2(acc[mt][nt][0], acc[mt][nt][1]);
            *(float2*)(C + (size_t)(r0 + 8) * N + cc) =
                make_float2(acc[mt][nt][2], acc[mt][nt][3]);
        }
    }
}

// ---------------- RoPE + scatter to head-major Q/K/V --------------------
__global__ __launch_bounds__(256) void rope_scatter2(
    const float* __restrict__ cosb, const float* __restrict__ sinb) {
    int tid = blockIdx.x * blockDim.x + threadIdx.x;
    if (tid >= T_SEQ * NH * HD) return;
    int d = tid & 63;
    int h = (tid >> 6) & 15;
    int t = tid >> 10;
    const float* row = g_qk + (size_t)t * QK_N + h * 128;
    float c = cosb[t * HD + d];
    float s = sinb[t * HD + d];
    int pd = (d < 32) ? d + 32 : d - 32;
    float sgn = (d < 32) ? -1.0f : 1.0f;

    float q = row[d];
    float qr = sgn * row[pd];
    float k = row[64 + d];
    float kr = sgn * row[64 + pd];
    size_t o = ((size_t)h * T_SEQ + t) * HD + d;
    g_Q[o] = q * c + qr * s;
    g_K[o] = k * c + kr * s;
    g_V[o] = g_vt[(size_t)t * C_DIM + h * HD + d];
}

// ---------------- per-chunk sums: KV outer, Ksum(fp64), Vsum ------------
__global__ __launch_bounds__(256) void chunk_sums() {
    extern __shared__ float smf2[];
    float* Ks = smf2;
    float* Vs = smf2 + CHUNK * HD;
    const int c = blockIdx.x, h = blockIdx.y, tid = threadIdx.x;
    const float* Kg = g_K + ((size_t)h * T_SEQ + c * CHUNK) * HD;
    const float* Vg = g_V + ((size_t)h * T_SEQ + c * CHUNK) * HD;
    for (int it = tid; it < CHUNK * HD / 4; it += 256) {
        ((float4*)Ks)[it] = ((const float4*)Kg)[it];
        ((float4*)Vs)[it] = ((const float4*)Vg)[it];
    }
    __syncthreads();

    const int d0 = (tid >> 3) << 1;
    const int e0 = (tid & 7) * 8;
    float acc0[8], acc1[8];
#pragma unroll
    for (int u = 0; u < 8; u++) { acc0[u] = 0.0f; acc1[u] = 0.0f; }
    for (int j = 0; j < CHUNK; j++) {
        float2 kk = *(const float2*)&Ks[j * HD + d0];
        float v[8];
        *(float4*)&v[0] = *(const float4*)&Vs[j * HD + e0];
        *(float4*)&v[4] = *(const float4*)&Vs[j * HD + e0 + 4];
#pragma unroll
        for (int u = 0; u < 8; u++) {
            acc0[u] += kk.x * v[u];
            acc1[u] += kk.y * v[u];
        }
    }
    float* out = g_KVc + ((size_t)h * NCHUNK + c) * (HD * HD);
    *(float4*)&out[(d0 + 0) * HD + e0]     = make_float4(acc0[0], acc0[1], acc0[2], acc0[3]);
    *(float4*)&out[(d0 + 0) * HD + e0 + 4] = make_float4(acc0[4], acc0[5], acc0[6], acc0[7]);
    *(float4*)&out[(d0 + 1) * HD + e0]     = make_float4(acc1[0], acc1[1], acc1[2], acc1[3]);
    *(float4*)&out[(d0 + 1) * HD + e0 + 4] = make_float4(acc1[4], acc1[5], acc1[6], acc1[7]);

    if (tid < HD) {
        double s0 = 0.0, s1 = 0.0;
        for (int j = 0; j < CHUNK; j += 2) {
            s0 += (double)Ks[j * HD + tid];
            s1 += (double)Ks[(j + 1) * HD + tid];
        }
        g_Ksc[((size_t)h * NCHUNK + c) * HD + tid] = s0 + s1;
    } else if (tid < 2 * HD) {
        int e = tid - HD;
        float s = 0.0f;
        for (int j = 0; j < CHUNK; j++) s += Vs[j * HD + e];
        g_Vsc[((size_t)h * NCHUNK + c) * HD + e] = s;
    }
}

// ---------------- chunk_score: scores -> g_S, fp64 den -> g_den ---------
__global__ __launch_bounds__(256, 2) void chunk_score() {
    extern __shared__ char smraw[];
    double* KspD  = (double*)smraw;                  // [64]
    double* kcumH = (double*)(smraw + 512);          // [64][64] (one j-half)
    float* Qst = (float*)(smraw + 512 + 32768);      // [64][128] d-major
    float* Kst = Qst + HD * CHUNK;                   // [64][128]

    const int c = blockIdx.x, h = blockIdx.y, tid = threadIdx.x;
    const float* Qg = g_Q + ((size_t)h * T_SEQ + c * CHUNK) * HD;
    const float* Kg = g_K + ((size_t)h * T_SEQ + c * CHUNK) * HD;

    for (int it = tid; it < CHUNK * HD / 4; it += 256) {
        int t = it >> 4;
        int d4 = (it & 15) * 4;
        float4 q4 = ((const float4*)(Qg + t * HD))[it & 15];
        float4 k4 = ((const float4*)(Kg + t * HD))[it & 15];
        Qst[(d4 + 0) * CHUNK + t] = q4.x; Qst[(d4 + 1) * CHUNK + t] = q4.y;
        Qst[(d4 + 2) * CHUNK + t] = q4.z; Qst[(d4 + 3) * CHUNK + t] = q4.w;
        Kst[(d4 + 0) * CHUNK + t] = k4.x; Kst[(d4 + 1) * CHUNK + t] = k4.y;
        Kst[(d4 + 2) * CHUNK + t] = k4.z; Kst[(d4 + 3) * CHUNK + t] = k4.w;
    }
    if (tid < HD) {
        double s = 0.0;
        for (int cp = 0; cp < c; cp++)
            s += g_Ksc[((size_t)h * NCHUNK + cp) * HD + tid];
        KspD[tid] = s;
    }
    __syncthreads();

#pragma unroll 1
    for (int half = 0; half < 2; half++) {
        if (tid < HD) {
            const int d = tid;
            double acc = KspD[d];
            for (int jj = 0; jj < 64; jj++) {
                acc += (double)Kst[d * CHUNK + half * 64 + jj];
                kcumH[d * 64 + jj] = acc;
            }
            KspD[d] = acc;
        }
        __syncthreads();
        if (tid < 64) {
            const int il = tid;
            const int i = half * 64 + il;
            double s0 = (double)(c * CHUNK + i + 1), s1 = 0.0, s2 = 0.0, s3 = 0.0;
            for (int d = 0; d < HD; d += 4) {
                s0 += (double)Qst[(d + 0) * CHUNK + i] * kcumH[(d + 0) * 64 + il];
                s1 += (double)Qst[(d + 1) * CHUNK + i] * kcumH[(d + 1) * 64 + il];
                s2 += (double)Qst[(d + 2) * CHUNK + i] * kcumH[(d + 2) * 64 + il];
                s3 += (double)Qst[(d + 3) * CHUNK + i] * kcumH[(d + 3) * 64 + il];
            }
            g_den[(size_t)h * T_SEQ + c * CHUNK + i] = (s0 + s1) + (s2 + s3);
        }
        __syncthreads();
    }

    {
        float* Sg = g_S + ((size_t)h * NCHUNK + c) * (CHUNK * CHUNK);
        const int tx = tid & 15;
        const int ty = tid >> 4;
        const int i0 = tx * 8, j0 = ty * 8;
        float acc[8][8];
#pragma unroll
        for (int jj = 0; jj < 8; jj++)
#pragma unroll
            for (int ii = 0; ii < 8; ii++) acc[jj][ii] = 1.0f;
        for (int d = 0; d < HD; d++) {
            float q[8], k[8];
            *(float4*)&q[0] = *(const float4*)&Qst[d * CHUNK + i0];
            *(float4*)&q[4] = *(const float4*)&Qst[d * CHUNK + i0 + 4];
            *(float4*)&k[0] = *(const float4*)&Kst[d * CHUNK + j0];
            *(float4*)&k[4] = *(const float4*)&Kst[d * CHUNK + j0 + 4];
#pragma unroll
            for (int jj = 0; jj < 8; jj++)
#pragma unroll
                for (int ii = 0; ii < 8; ii++) acc[jj][ii] += k[jj] * q[ii];
        }
#pragma unroll
        for (int jj = 0; jj < 8; jj++) {
            int j = j0 + jj;
            float v[8];
#pragma unroll
            for (int ii = 0; ii < 8; ii++)
                v[ii] = (j <= i0 + ii) ? acc[jj][ii] : 0.0f;
            float4* sp = (float4*)&Sg[j * CHUNK + i0];
            sp[0] = make_float4(v[0], v[1], v[2], v[3]);
            sp[1] = make_float4(v[4], v[5], v[6], v[7]);
        }
    }
}

// ---------------- chunk_out: numerators + divide ------------------------
__global__ __launch_bounds__(256, 2) void chunk_out() {
    extern __shared__ char smraw[];
    float* Sct = (float*)smraw;               // [128][128]
    float* Vs  = Sct + CHUNK * CHUNK;         // [128][64]
    float* KVp = Vs + CHUNK * HD;             // [64][64]

    const int c = blockIdx.x, h = blockIdx.y, tid = threadIdx.x;
    const float* Sg = g_S + ((size_t)h * NCHUNK + c) * (CHUNK * CHUNK);
    const float* Vg = g_V + ((size_t)h * T_SEQ + c * CHUNK) * HD;

    for (int it = tid; it < CHUNK * CHUNK / 4; it += 256)
        ((float4*)Sct)[it] = ((const float4*)Sg)[it];
    for (int it = tid; it < CHUNK * HD / 4; it += 256)
        ((float4*)Vs)[it] = ((const float4*)Vg)[it];

    {
        float kv[16];
#pragma unroll
        for (int u = 0; u < 16; u++) kv[u] = 0.0f;
        for (int cp = 0; cp < c; cp++) {
            const float* p = g_KVc + ((size_t)h * NCHUNK + cp) * (HD * HD) + tid * 16;
#pragma unroll
            for (int u = 0; u < 16; u++) kv[u] += p[u];
        }
#pragma unroll
        for (int u = 0; u < 16; u++) KVp[tid * 16 + u] = kv[u];
    }
    __syncthreads();

    {
        const int ti = tid >> 3;
        const int i0 = ti * 4;
        const int e0 = (tid & 7) * 8;

        float vsp[8];
#pragma unroll
        for (int u = 0; u < 8; u++) vsp[u] = 0.0f;
        for (int cp = 0; cp < c; cp++) {
            const float* p = g_Vsc + ((size_t)h * NCHUNK + cp) * HD + e0;
#pragma unroll
            for (int u = 0; u < 8; u++) vsp[u] += p[u];
        }

        float acc[4][8];
#pragma unroll
        for (int ii = 0; ii < 4; ii++)
#pragma unroll
            for (int ee = 0; ee < 8; ee++) acc[ii][ee] = 0.0f;
        const float* Qg = g_Q + ((size_t)h * T_SEQ + c * CHUNK) * HD;
        for (int d = 0; d < HD; d++) {
            float q[4], kv[8];
            q[0] = Qg[(i0 + 0) * HD + d];
            q[1] = Qg[(i0 + 1) * HD + d];
            q[2] = Qg[(i0 + 2) * HD + d];
            q[3] = Qg[(i0 + 3) * HD + d];
            *(float4*)&kv[0] = *(const float4*)&KVp[d * HD + e0];
            *(float4*)&kv[4] = *(const float4*)&KVp[d * HD + e0 + 4];
#pragma unroll
            for (int ii = 0; ii < 4; ii++)
#pragma unroll
                for (int ee = 0; ee < 8; ee++) acc[ii][ee] += q[ii] * kv[ee];
        }
        for (int j = 0; j < CHUNK; j++) {
            float sv[4], v[8];
            *(float4*)&sv[0] = *(const float4*)&Sct[j * CHUNK + i0];
            *(float4*)&v[0] = *(const float4*)&Vs[j * HD + e0];
            *(float4*)&v[4] = *(const float4*)&Vs[j * HD + e0 + 4];
#pragma unroll
            for (int ii = 0; ii < 4; ii++)
#pragma unroll
                for (int ee = 0; ee < 8; ee++) acc[ii][ee] += sv[ii] * v[ee];
        }
#pragma unroll
        for (int ii = 0; ii < 4; ii++) {
            int i = i0 + ii;
            int t = c * CHUNK + i;
            double inv = 1.0 / g_den[(size_t)h * T_SEQ + c * CHUNK + i];
            float o[8];
#pragma unroll
            for (int ee = 0; ee < 8; ee++)
                o[ee] = (float)((double)(acc[ii][ee] + vsp[ee]) * inv);
            float4* yp = (float4*)(g_Y + (size_t)t * C_DIM + h * HD + e0);
            yp[0] = make_float4(o[0], o[1], o[2], o[3]);
            yp[1] = make_float4(o[4], o[5], o[6], o[7]);
        }
    }
}

// ---------------- launch ------------------------------------------------
extern "C" void kernel_launch(void* const* d_in, const int* in_sizes, int n_in,
                              void* d_out, int out_size) {
    const float* x      = (const float*)d_in[0];
    const float* w_attn = (const float*)d_in[1];
    const float* w_proj = (const float*)d_in[2];
    const float* cosb   = (const float*)d_in[3];
    const float* sinb   = (const float*)d_in[4];
    float* out = (float*)d_out;

    void *p_qk, *p_vt, *p_Y;
    cudaGetSymbolAddress(&p_qk, g_qk);
    cudaGetSymbolAddress(&p_vt, g_vt);
    cudaGetSymbolAddress(&p_Y, g_Y);

    int smem_gemm  = 16384 * 4;
    int smem_sums  = 2 * CHUNK * HD * (int)sizeof(float);          // 64K
    int smem_score = 512 + 32768 + 32768 + 32768;                  // 98816
    int smem_out   = (CHUNK * CHUNK + CHUNK * HD + HD * HD)
                     * (int)sizeof(float);                         // 114688
    cudaFuncSetAttribute(gemm_mma3<0>, cudaFuncAttributeMaxDynamicSharedMemorySize,
                         smem_gemm);
    cudaFuncSetAttribute(gemm_mma3<1>, cudaFuncAttributeMaxDynamicSharedMemorySize,
                         smem_gemm);
    cudaFuncSetAttribute(chunk_sums, cudaFuncAttributeMaxDynamicSharedMemorySize,
                         smem_sums);
    cudaFuncSetAttribute(chunk_score, cudaFuncAttributeMaxDynamicSharedMemorySize,
                         smem_score);
    cudaFuncSetAttribute(chunk_out, cudaFuncAttributeMaxDynamicSharedMemorySize,
                         smem_out);

    // 1a) q|k = x @ w_attn_qk^T  (SIMT fp32 via FFMA2; bit-identical math)
    sgemm_qk<<<dim3(QK_N / 128, T_SEQ / 128), 256>>>(
        x, w_attn, (float*)p_qk, T_SEQ, QK_N, C_DIM);
    // 1b) v = x @ w_attn_v^T     (tf32 mma, unamplified path)
    gemm_mma3<1><<<dim3(C_DIM / 128, T_SEQ / 128), 256, smem_gemm>>>(
        x, w_attn, (float*)p_vt, T_SEQ, C_DIM, C_DIM);
    // 2) rope + scatter
    rope_scatter2<<<(T_SEQ * NH * HD + 255) / 256, 256>>>(cosb, sinb);
    // 3) chunk sums
    chunk_sums<<<dim3(NCHUNK, NH), 256, smem_sums>>>();
    // 4a) scores + fp64 denominators
    chunk_score<<<dim3(NCHUNK, NH), 256, smem_score>>>();
    // 4b) numerators + divide
    chunk_out<<<dim3(NCHUNK, NH), 256, smem_out>>>();
    // 5) out = Y @ w_proj^T      (tf32 mma)
    gemm_mma3<0><<<dim3(C_DIM / 128, T_SEQ / 128), 256, smem_gemm>>>(
        (const float*)p_Y, w_proj, out, T_SEQ, C_DIM, C_DIM);
}

// round 17
// speedup vs baseline: 1.6296x; 1.0224x over previous
#include <cuda_runtime.h>
#include <cstdint>
#include <cstddef>

#define T_SEQ 2048
#define NH 16
#define HD 64
#define C_DIM 1024
#define QK_N 2048
#define CHUNK 128
#define NCHUNK (T_SEQ / CHUNK)

// ---------------- scratch (static __device__, no allocs) ----------------
__device__ float  g_qk[T_SEQ * QK_N];
__device__ float  g_vt[T_SEQ * C_DIM];
__device__ float  g_Q[NH * T_SEQ * HD];
__device__ float  g_K[NH * T_SEQ * HD];
__device__ float  g_V[NH * T_SEQ * HD];
__device__ float  g_KVc[NH * NCHUNK * HD * HD];
__device__ double g_Ksc[NH * NCHUNK * HD];
__device__ float  g_Vsc[NH * NCHUNK * HD];
__device__ float  g_S[NH * NCHUNK * CHUNK * CHUNK];   // 16.8MB scores
__device__ double g_den[NH * T_SEQ];                  // fp64 denominators
__device__ float  g_Y[T_SEQ * C_DIM];

// ====== SIMT fp32 NT GEMM (q/k), FFMA2 + global prefetch ================
// Accumulation chains bit-identical to the proven SIMT kernel.
__global__ __launch_bounds__(256, 1) void sgemm_qk(
    const float* __restrict__ A, const float* __restrict__ B,
    float* __restrict__ C, int M, int N, int K) {
    __shared__ float As[8][128];
    __shared__ float Bs[8][128];
    const int bm = blockIdx.y * 128;
    const int bn = blockIdx.x * 128;
    const int tid = threadIdx.x;
    const int tx = tid & 15;
    const int ty = tid >> 4;
    const int lr = tid >> 1;
    const int lk = (tid & 1) << 2;

    const int gb = bn + lr;
    const int brow = ((gb >> 7) * 192) + (gb & 127);
    const float* Ap = A + (size_t)(bm + lr) * K + lk;
    const float* Bp = B + (size_t)brow * K + lk;

    unsigned long long acc2[8][4];   // packed {acc[i][2jp], acc[i][2jp+1]}
#pragma unroll
    for (int i = 0; i < 8; i++)
#pragma unroll
        for (int jp = 0; jp < 4; jp++) acc2[i][jp] = 0ull;

    float4 a4 = *(const float4*)(Ap);
    float4 b4 = *(const float4*)(Bp);
    for (int k0 = 0; k0 < K; k0 += 8) {
        As[lk + 0][lr] = a4.x; As[lk + 1][lr] = a4.y;
        As[lk + 2][lr] = a4.z; As[lk + 3][lr] = a4.w;
        Bs[lk + 0][lr] = b4.x; Bs[lk + 1][lr] = b4.y;
        Bs[lk + 2][lr] = b4.z; Bs[lk + 3][lr] = b4.w;
        __syncthreads();
        // prefetch next k-block while computing this one
        float4 a4n, b4n;
        if (k0 + 8 < K) {
            a4n = *(const float4*)(Ap + k0 + 8);
            b4n = *(const float4*)(Bp + k0 + 8);
        }
#pragma unroll
        for (int kk = 0; kk < 8; kk++) {
            float a[8];
            *(float4*)&a[0] = *(const float4*)&As[kk][ty * 8];
            *(float4*)&a[4] = *(const float4*)&As[kk][ty * 8 + 4];
            unsigned long long b2[4];
            {
                ulonglong2 p0 = *(const ulonglong2*)&Bs[kk][tx * 8];
                ulonglong2 p1 = *(const ulonglong2*)&Bs[kk][tx * 8 + 4];
                b2[0] = p0.x; b2[1] = p0.y; b2[2] = p1.x; b2[3] = p1.y;
            }
            unsigned long long a2[8];
#pragma unroll
            for (int i = 0; i < 8; i++)
                asm("mov.b64 %0, {%1, %1};" : "=l"(a2[i]) : "f"(a[i]));
#pragma unroll
            for (int i = 0; i < 8; i++)
#pragma unroll
                for (int jp = 0; jp < 4; jp++)
                    asm("fma.rn.f32x2 %0, %1, %2, %0;"
                        : "+l"(acc2[i][jp]) : "l"(a2[i]), "l"(b2[jp]));
        }
        __syncthreads();
        a4 = a4n; b4 = b4n;
    }
#pragma unroll
    for (int i = 0; i < 8; i++) {
        float o[8];
#pragma unroll
        for (int jp = 0; jp < 4; jp++)
            asm("mov.b64 {%0, %1}, %2;"
                : "=f"(o[2 * jp]), "=f"(o[2 * jp + 1]) : "l"(acc2[i][jp]));
        float4* cp = (float4*)(C + (size_t)(bm + ty * 8 + i) * N + bn + tx * 8);
        cp[0] = make_float4(o[0], o[1], o[2], o[3]);
        cp[1] = make_float4(o[4], o[5], o[6], o[7]);
    }
}

// =================== tf32 mma.sync helpers (sm_80+ PTX) =================
__device__ __forceinline__ void split2(float x, uint32_t& h, uint32_t& l) {
    asm("cvt.rna.tf32.f32 %0, %1;" : "=r"(h) : "f"(x));
    float r = x - __uint_as_float(h);
    asm("cvt.rna.tf32.f32 %0, %1;" : "=r"(l) : "f"(r));
}

__device__ __forceinline__ void mma_tf32(float* d, const uint32_t* a,
                                         const uint32_t* b) {
    asm volatile(
        "mma.sync.aligned.m16n8k8.row.col.f32.tf32.tf32.f32 "
        "{%0,%1,%2,%3}, {%4,%5,%6,%7}, {%8,%9}, {%0,%1,%2,%3};"
        : "+f"(d[0]), "+f"(d[1]), "+f"(d[2]), "+f"(d[3])
        : "r"(a[0]), "r"(a[1]), "r"(a[2]), "r"(a[3]), "r"(b[0]), "r"(b[1]));
}

#define CP_ASYNC16(dst, src) \
    asm volatile("cp.async.cg.shared.global [%0], [%1], 16;" \
                 :: "r"(dst), "l"(src))
#define CP_COMMIT() asm volatile("cp.async.commit_group;" ::: "memory")
#define CP_WAIT1()  asm volatile("cp.async.wait_group 1;" ::: "memory")
#define CP_WAIT0()  asm volatile("cp.async.wait_group 0;" ::: "memory")

// ======= tf32 mma NT GEMM (3-product).  REMAP=1: B row gathered for v ===
template <int REMAP>
__global__ __launch_bounds__(256, 1) void gemm_mma3(
    const float* __restrict__ A, const float* __restrict__ B,
    float* __restrict__ C, int M, int N, int K) {
    extern __shared__ float smf[];
    float* As = smf;
    float* Bs = smf + 8192;
    const uint32_t smA_u32 = (uint32_t)__cvta_generic_to_shared(As);
    const uint32_t smB_u32 = (uint32_t)__cvta_generic_to_shared(Bs);

    const int tid = threadIdx.x;
    const int wid = tid >> 5;
    const int lane = tid & 31;
    const int bm = blockIdx.y * 128;
    const int bn = blockIdx.x * 128;
    const int warpM = (wid >> 2) * 64;
    const int warpN = (wid & 3) * 32;
    const int nk = K >> 5;

    const int lr = tid >> 1;
    const int j0 = (tid & 1) * 4;
    const int lrx = lr & 7;
    const int gb = bn + lr;
    const int brow = REMAP ? (((gb >> 6) * 192) + 128 + (gb & 63)) : gb;
    const float* Asrc = A + (size_t)(bm + lr) * K;
    const float* Bsrc = B + (size_t)brow * K;

    float acc[4][4][4];
#pragma unroll
    for (int mt = 0; mt < 4; mt++)
#pragma unroll
        for (int nt = 0; nt < 4; nt++)
#pragma unroll
            for (int u = 0; u < 4; u++) acc[mt][nt][u] = 0.0f;

    {
        const uint32_t ab = smA_u32 + lr * 128;
        const uint32_t bb = smB_u32 + lr * 128;
#pragma unroll
        for (int j = 0; j < 4; j++) {
            int c4 = j0 + j;
            int swc = (c4 ^ lrx) * 16;
            CP_ASYNC16(ab + swc, Asrc + c4 * 4);
            CP_ASYNC16(bb + swc, Bsrc + c4 * 4);
        }
        CP_COMMIT();
    }

    for (int it = 0; it < nk; it++) {
        if (it + 1 < nk) {
            const int nb = (it + 1) & 1;
            const int kblk = (it + 1) << 5;
            const uint32_t ab = smA_u32 + nb * 16384 + lr * 128;
            const uint32_t bb = smB_u32 + nb * 16384 + lr * 128;
#pragma unroll
            for (int j = 0; j < 4; j++) {
                int c4 = j0 + j;
                int swc = (c4 ^ lrx) * 16;
                CP_ASYNC16(ab + swc, Asrc + kblk + c4 * 4);
                CP_ASYNC16(bb + swc, Bsrc + kblk + c4 * 4);
            }
            CP_COMMIT();
            CP_WAIT1();
        } else {
            CP_WAIT0();
        }
        __syncthreads();

        const float* Ab = As + (it & 1) * 4096;
        const float* Bb = Bs + (it & 1) * 4096;
#pragma unroll
        for (int ks = 0; ks < 4; ks++) {
            uint32_t bh[4][2], bl[4][2];
#pragma unroll
            for (int nt = 0; nt < 4; nt++) {
                int n0 = warpN + nt * 8 + (lane >> 2);
                const float* bp = Bb + n0 * 32;
                int s0 = ((2 * ks) ^ (n0 & 7)) * 4 + (lane & 3);
                int s1 = ((2 * ks + 1) ^ (n0 & 7)) * 4 + (lane & 3);
                split2(bp[s0], bh[nt][0], bl[nt][0]);
                split2(bp[s1], bh[nt][1], bl[nt][1]);
            }
#pragma unroll
            for (int mt = 0; mt < 4; mt++) {
                int r0 = warpM + mt * 16 + (lane >> 2);
                const float* ap0 = Ab + r0 * 32;
                const float* ap1 = ap0 + 8 * 32;
                int s0 = ((2 * ks) ^ (r0 & 7)) * 4 + (lane & 3);
                int s1 = ((2 * ks + 1) ^ (r0 & 7)) * 4 + (lane & 3);
                uint32_t ah[4], al[4];
                split2(ap0[s0], ah[0], al[0]);
                split2(ap1[s0], ah[1], al[1]);
                split2(ap0[s1], ah[2], al[2]);
                split2(ap1[s1], ah[3], al[3]);
#pragma unroll
                for (int nt = 0; nt < 4; nt++) {
                    mma_tf32(acc[mt][nt], ah, bh[nt]);
                    mma_tf32(acc[mt][nt], ah, bl[nt]);
                    mma_tf32(acc[mt][nt], al, bh[nt]);
                }
            }
        }
        __syncthreads();
    }

#pragma unroll
    for (int mt = 0; mt < 4; mt++) {
        int r0 = bm + warpM + mt * 16 + (lane >> 2);
#pragma unroll
        for (int nt = 0; nt < 4; nt++) {
            int cc = bn + warpN + nt * 8 + 2 * (lane & 3);
            *(float2*)(C + (size_t)r0 * N + cc) =
                make_float2(acc[mt][nt][0], acc[mt][nt][1]);
            *(float2*)(C + (size_t)(r0 + 8) * N + cc) =
                make_float2(acc[mt][nt][2], acc[mt][nt][3]);
        }
    }
}

// ---------------- fused RoPE + per-chunk sums ---------------------------
// Block (c,h): ropes its own 128x64 tile of Q/K/V (identical per-element
// expressions to the old rope kernel), writes g_Q/g_K/g_V, and computes
// KV outer / Ksum(fp64) / Vsum from the in-smem roped tiles.
__global__ __launch_bounds__(256) void rope_sums(
    const float* __restrict__ cosb, const float* __restrict__ sinb) {
    extern __shared__ float smf2[];
    float* Ks = smf2;               // [128][64]
    float* Vs = smf2 + CHUNK * HD;  // [128][64]
    const int c = blockIdx.x, h = blockIdx.y, tid = threadIdx.x;
    const int t0 = c * CHUNK;

    for (int it = tid; it < CHUNK * HD; it += 256) {
        int tl = it >> 6;
        int d = it & 63;
        int t = t0 + tl;
        const float* row = g_qk + (size_t)t * QK_N + h * 128;
        float cc = cosb[t * HD + d];
        float ss = sinb[t * HD + d];
        int pd = (d < 32) ? d + 32 : d - 32;
        float sgn = (d < 32) ? -1.0f : 1.0f;

        float q = row[d];
        float qr = sgn * row[pd];
        float k = row[64 + d];
        float kr = sgn * row[64 + pd];
        float qq = q * cc + qr * ss;
        float kk = k * cc + kr * ss;
        float vv = g_vt[(size_t)t * C_DIM + h * HD + d];
        size_t o = ((size_t)h * T_SEQ + t) * HD + d;
        g_Q[o] = qq;
        g_K[o] = kk;
        g_V[o] = vv;
        Ks[tl * HD + d] = kk;
        Vs[tl * HD + d] = vv;
    }
    __syncthreads();

    const int d0 = (tid >> 3) << 1;
    const int e0 = (tid & 7) * 8;
    float acc0[8], acc1[8];
#pragma unroll
    for (int u = 0; u < 8; u++) { acc0[u] = 0.0f; acc1[u] = 0.0f; }
    for (int j = 0; j < CHUNK; j++) {
        float2 kk = *(const float2*)&Ks[j * HD + d0];
        float v[8];
        *(float4*)&v[0] = *(const float4*)&Vs[j * HD + e0];
        *(float4*)&v[4] = *(const float4*)&Vs[j * HD + e0 + 4];
#pragma unroll
        for (int u = 0; u < 8; u++) {
            acc0[u] += kk.x * v[u];
            acc1[u] += kk.y * v[u];
        }
    }
    float* out = g_KVc + ((size_t)h * NCHUNK + c) * (HD * HD);
    *(float4*)&out[(d0 + 0) * HD + e0]     = make_float4(acc0[0], acc0[1], acc0[2], acc0[3]);
    *(float4*)&out[(d0 + 0) * HD + e0 + 4] = make_float4(acc0[4], acc0[5], acc0[6], acc0[7]);
    *(float4*)&out[(d0 + 1) * HD + e0]     = make_float4(acc1[0], acc1[1], acc1[2], acc1[3]);
    *(float4*)&out[(d0 + 1) * HD + e0 + 4] = make_float4(acc1[4], acc1[5], acc1[6], acc1[7]);

    if (tid < HD) {
        double s0 = 0.0, s1 = 0.0;
        for (int j = 0; j < CHUNK; j += 2) {
            s0 += (double)Ks[j * HD + tid];
            s1 += (double)Ks[(j + 1) * HD + tid];
        }
        g_Ksc[((size_t)h * NCHUNK + c) * HD + tid] = s0 + s1;
    } else if (tid < 2 * HD) {
        int e = tid - HD;
        float s = 0.0f;
        for (int j = 0; j < CHUNK; j++) s += Vs[j * HD + e];
        g_Vsc[((size_t)h * NCHUNK + c) * HD + e] = s;
    }
}

// ---------------- chunk_score: scores -> g_S, fp64 den -> g_den ---------
__global__ __launch_bounds__(256, 2) void chunk_score() {
    extern __shared__ char smraw[];
    double* KspD  = (double*)smraw;                  // [64]
    double* kcumH = (double*)(smraw + 512);          // [64][64] (one j-half)
    float* Qst = (float*)(smraw + 512 + 32768);      // [64][128] d-major
    float* Kst = Qst + HD * CHUNK;                   // [64][128]

    const int c = blockIdx.x, h = blockIdx.y, tid = threadIdx.x;
    const float* Qg = g_Q + ((size_t)h * T_SEQ + c * CHUNK) * HD;
    const float* Kg = g_K + ((size_t)h * T_SEQ + c * CHUNK) * HD;

    for (int it = tid; it < CHUNK * HD / 4; it += 256) {
        int t = it >> 4;
        int d4 = (it & 15) * 4;
        float4 q4 = ((const float4*)(Qg + t * HD))[it & 15];
        float4 k4 = ((const float4*)(Kg + t * HD))[it & 15];
        Qst[(d4 + 0) * CHUNK + t] = q4.x; Qst[(d4 + 1) * CHUNK + t] = q4.y;
        Qst[(d4 + 2) * CHUNK + t] = q4.z; Qst[(d4 + 3) * CHUNK + t] = q4.w;
        Kst[(d4 + 0) * CHUNK + t] = k4.x; Kst[(d4 + 1) * CHUNK + t] = k4.y;
        Kst[(d4 + 2) * CHUNK + t] = k4.z; Kst[(d4 + 3) * CHUNK + t] = k4.w;
    }
    if (tid < HD) {
        double s = 0.0;
        for (int cp = 0; cp < c; cp++)
            s += g_Ksc[((size_t)h * NCHUNK + cp) * HD + tid];
        KspD[tid] = s;
    }
    __syncthreads();

#pragma unroll 1
    for (int half = 0; half < 2; half++) {
        if (tid < HD) {
            const int d = tid;
            double acc = KspD[d];
            for (int jj = 0; jj < 64; jj++) {
                acc += (double)Kst[d * CHUNK + half * 64 + jj];
                kcumH[d * 64 + jj] = acc;
            }
            KspD[d] = acc;
        }
        __syncthreads();
        if (tid < 64) {
            const int il = tid;
            const int i = half * 64 + il;
            double s0 = (double)(c * CHUNK + i + 1), s1 = 0.0, s2 = 0.0, s3 = 0.0;
            for (int d = 0; d < HD; d += 4) {
                s0 += (double)Qst[(d + 0) * CHUNK + i] * kcumH[(d + 0) * 64 + il];
                s1 += (double)Qst[(d + 1) * CHUNK + i] * kcumH[(d + 1) * 64 + il];
                s2 += (double)Qst[(d + 2) * CHUNK + i] * kcumH[(d + 2) * 64 + il];
                s3 += (double)Qst[(d + 3) * CHUNK + i] * kcumH[(d + 3) * 64 + il];
            }
            g_den[(size_t)h * T_SEQ + c * CHUNK + i] = (s0 + s1) + (s2 + s3);
        }
        __syncthreads();
    }

    {
        float* Sg = g_S + ((size_t)h * NCHUNK + c) * (CHUNK * CHUNK);
        const int tx = tid & 15;
        const int ty = tid >> 4;
        const int i0 = tx * 8, j0 = ty * 8;
        float acc[8][8];
#pragma unroll
        for (int jj = 0; jj < 8; jj++)
#pragma unroll
            for (int ii = 0; ii < 8; ii++) acc[jj][ii] = 1.0f;
        for (int d = 0; d < HD; d++) {
            float q[8], k[8];
            *(float4*)&q[0] = *(const float4*)&Qst[d * CHUNK + i0];
            *(float4*)&q[4] = *(const float4*)&Qst[d * CHUNK + i0 + 4];
            *(float4*)&k[0] = *(const float4*)&Kst[d * CHUNK + j0];
            *(float4*)&k[4] = *(const float4*)&Kst[d * CHUNK + j0 + 4];
#pragma unroll
            for (int jj = 0; jj < 8; jj++)
#pragma unroll
                for (int ii = 0; ii < 8; ii++) acc[jj][ii] += k[jj] * q[ii];
        }
#pragma unroll
        for (int jj = 0; jj < 8; jj++) {
            int j = j0 + jj;
            float v[8];
#pragma unroll
            for (int ii = 0; ii < 8; ii++)
                v[ii] = (j <= i0 + ii) ? acc[jj][ii] : 0.0f;
            float4* sp = (float4*)&Sg[j * CHUNK + i0];
            sp[0] = make_float4(v[0], v[1], v[2], v[3]);
            sp[1] = make_float4(v[4], v[5], v[6], v[7]);
        }
    }
}

// ---------------- chunk_out: numerators + divide ------------------------
__global__ __launch_bounds__(256, 2) void chunk_out() {
    extern __shared__ char smraw[];
    float* Sct = (float*)smraw;               // [128][128]
    float* Vs  = Sct + CHUNK * CHUNK;         // [128][64]
    float* KVp = Vs + CHUNK * HD;             // [64][64]

    const int c = blockIdx.x, h = blockIdx.y, tid = threadIdx.x;
    const float* Sg = g_S + ((size_t)h * NCHUNK + c) * (CHUNK * CHUNK);
    const float* Vg = g_V + ((size_t)h * T_SEQ + c * CHUNK) * HD;

    for (int it = tid; it < CHUNK * CHUNK / 4; it += 256)
        ((float4*)Sct)[it] = ((const float4*)Sg)[it];
    for (int it = tid; it < CHUNK * HD / 4; it += 256)
        ((float4*)Vs)[it] = ((const float4*)Vg)[it];

    {
        float kv[16];
#pragma unroll
        for (int u = 0; u < 16; u++) kv[u] = 0.0f;
        for (int cp = 0; cp < c; cp++) {
            const float* p = g_KVc + ((size_t)h * NCHUNK + cp) * (HD * HD) + tid * 16;
#pragma unroll
            for (int u = 0; u < 16; u++) kv[u] += p[u];
        }
#pragma unroll
        for (int u = 0; u < 16; u++) KVp[tid * 16 + u] = kv[u];
    }
    __syncthreads();

    {
        const int ti = tid >> 3;
        const int i0 = ti * 4;
        const int e0 = (tid & 7) * 8;

        float vsp[8];
#pragma unroll
        for (int u = 0; u < 8; u++) vsp[u] = 0.0f;
        for (int cp = 0; cp < c; cp++) {
            const float* p = g_Vsc + ((size_t)h * NCHUNK + cp) * HD + e0;
#pragma unroll
            for (int u = 0; u < 8; u++) vsp[u] += p[u];
        }

        float acc[4][8];
#pragma unroll
        for (int ii = 0; ii < 4; ii++)
#pragma unroll
            for (int ee = 0; ee < 8; ee++) acc[ii][ee] = 0.0f;
        const float* Qg = g_Q + ((size_t)h * T_SEQ + c * CHUNK) * HD;
        for (int d = 0; d < HD; d++) {
            float q[4], kv[8];
            q[0] = Qg[(i0 + 0) * HD + d];
            q[1] = Qg[(i0 + 1) * HD + d];
            q[2] = Qg[(i0 + 2) * HD + d];
            q[3] = Qg[(i0 + 3) * HD + d];
            *(float4*)&kv[0] = *(const float4*)&KVp[d * HD + e0];
            *(float4*)&kv[4] = *(const float4*)&KVp[d * HD + e0 + 4];
#pragma unroll
            for (int ii = 0; ii < 4; ii++)
#pragma unroll
                for (int ee = 0; ee < 8; ee++) acc[ii][ee] += q[ii] * kv[ee];
        }
        for (int j = 0; j < CHUNK; j++) {
            float sv[4], v[8];
            *(float4*)&sv[0] = *(const float4*)&Sct[j * CHUNK + i0];
            *(float4*)&v[0] = *(const float4*)&Vs[j * HD + e0];
            *(float4*)&v[4] = *(const float4*)&Vs[j * HD + e0 + 4];
#pragma unroll
            for (int ii = 0; ii < 4; ii++)
#pragma unroll
                for (int ee = 0; ee < 8; ee++) acc[ii][ee] += sv[ii] * v[ee];
        }
#pragma unroll
        for (int ii = 0; ii < 4; ii++) {
            int i = i0 + ii;
            int t = c * CHUNK + i;
            double inv = 1.0 / g_den[(size_t)h * T_SEQ + c * CHUNK + i];
            float o[8];
#pragma unroll
            for (int ee = 0; ee < 8; ee++)
                o[ee] = (float)((double)(acc[ii][ee] + vsp[ee]) * inv);
            float4* yp = (float4*)(g_Y + (size_t)t * C_DIM + h * HD + e0);
            yp[0] = make_float4(o[0], o[1], o[2], o[3]);
            yp[1] = make_float4(o[4], o[5], o[6], o[7]);
        }
    }
}

// ---------------- launch ------------------------------------------------
extern "C" void kernel_launch(void* const* d_in, const int* in_sizes, int n_in,
                              void* d_out, int out_size) {
    const float* x      = (const float*)d_in[0];
    const float* w_attn = (const float*)d_in[1];
    const float* w_proj = (const float*)d_in[2];
    const float* cosb   = (const float*)d_in[3];
    const float* sinb   = (const float*)d_in[4];
    float* out = (float*)d_out;

    void *p_qk, *p_vt, *p_Y;
    cudaGetSymbolAddress(&p_qk, g_qk);
    cudaGetSymbolAddress(&p_vt, g_vt);
    cudaGetSymbolAddress(&p_Y, g_Y);

    int smem_gemm  = 16384 * 4;
    int smem_sums  = 2 * CHUNK * HD * (int)sizeof(float);          // 64K
    int smem_score = 512 + 32768 + 32768 + 32768;                  // 98816
    int smem_out   = (CHUNK * CHUNK + CHUNK * HD + HD * HD)
                     * (int)sizeof(float);                         // 114688
    cudaFuncSetAttribute(gemm_mma3<0>, cudaFuncAttributeMaxDynamicSharedMemorySize,
                         smem_gemm);
    cudaFuncSetAttribute(gemm_mma3<1>, cudaFuncAttributeMaxDynamicSharedMemorySize,
                         smem_gemm);
    cudaFuncSetAttribute(rope_sums, cudaFuncAttributeMaxDynamicSharedMemorySize,
                         smem_sums);
    cudaFuncSetAttribute(chunk_score, cudaFuncAttributeMaxDynamicSharedMemorySize,
                         smem_score);
    cudaFuncSetAttribute(chunk_out, cudaFuncAttributeMaxDynamicSharedMemorySize,
                         smem_out);

    // 1a) q|k = x @ w_attn_qk^T  (SIMT fp32 FFMA2 + prefetch)
    sgemm_qk<<<dim3(QK_N / 128, T_SEQ / 128), 256>>>(
        x, w_attn, (float*)p_qk, T_SEQ, QK_N, C_DIM);
    // 1b) v = x @ w_attn_v^T     (tf32 mma, unamplified path)
    gemm_mma3<1><<<dim3(C_DIM / 128, T_SEQ / 128), 256, smem_gemm>>>(
        x, w_attn, (float*)p_vt, T_SEQ, C_DIM, C_DIM);
    // 2) fused rope + chunk sums
    rope_sums<<<dim3(NCHUNK, NH), 256, smem_sums>>>(cosb, sinb);
    // 3) scores + fp64 denominators
    chunk_score<<<dim3(NCHUNK, NH), 256, smem_score>>>();
    // 4) numerators + divide
    chunk_out<<<dim3(NCHUNK, NH), 256, smem_out>>>();
    // 5) out = Y @ w_proj^T      (tf32 mma)
    gemm_mma3<0><<<dim3(C_DIM / 128, T_SEQ / 128), 256, smem_gemm>>>(
        (const float*)p_Y, w_proj, out, T_SEQ, C_DIM, C_DIM);
}